// round 2
// baseline (speedup 1.0000x reference)
#include <cuda_runtime.h>

#define B_SZ   64
#define H_SZ   256
#define G_SZ   768            // 3*H
#define T_ENC  48
#define T_DEC  32
#define V_OUT  32000
#define M_ENC  (B_SZ * T_ENC) // 3072
#define M_DEC  (B_SZ * T_DEC) // 2048
#define NBLK_REC 64

// ---------------- device scratch (static, no runtime allocation) ----------
__device__ float g_xg_enc[M_ENC * G_SZ];   // [b*48+t][768]
__device__ float g_xg_dec[M_DEC * G_SZ];   // [b*32+t][768]
__device__ float g_h[2][B_SZ * H_SZ];      // double-buffered hidden state
__device__ float g_dech[M_DEC * H_SZ];     // decoder hidden outputs
__device__ unsigned g_ticket;              // monotonic across graph replays
__device__ unsigned g_flag;                // monotonic generation counter

// ---------------- helpers --------------------------------------------------
__device__ __forceinline__ unsigned f2tf32(float x) {
    unsigned r; asm("cvt.rna.tf32.f32 %0, %1;" : "=r"(r) : "f"(x)); return r;
}

__device__ __forceinline__ void mma_tf32(float* d, const unsigned* a,
                                         unsigned b0, unsigned b1) {
    asm volatile(
        "mma.sync.aligned.m16n8k8.row.col.f32.tf32.tf32.f32 "
        "{%0,%1,%2,%3}, {%4,%5,%6,%7}, {%8,%9}, {%0,%1,%2,%3};"
        : "+f"(d[0]), "+f"(d[1]), "+f"(d[2]), "+f"(d[3])
        : "r"(a[0]), "r"(a[1]), "r"(a[2]), "r"(a[3]), "r"(b0), "r"(b1));
}

__device__ __forceinline__ void fma2(unsigned long long& d,
                                     unsigned long long a, unsigned long long b) {
    asm("fma.rn.f32x2 %0, %1, %2, %0;" : "+l"(d) : "l"(a), "l"(b));
}

__device__ __forceinline__ float red2(unsigned long long a, unsigned long long b) {
    float x0, x1, y0, y1;
    asm("mov.b64 {%0,%1}, %2;" : "=f"(x0), "=f"(x1) : "l"(a));
    asm("mov.b64 {%0,%1}, %2;" : "=f"(y0), "=f"(y1) : "l"(b));
    return (x0 + x1) + (y0 + y1);
}

// Monotonic ticket barrier across NBLK_REC co-resident blocks.
// Correct across CUDA-graph replays (no state reset required).
__device__ __forceinline__ void grid_barrier() {
    __syncthreads();
    if (threadIdx.x == 0) {
        __threadfence();
        unsigned t;
        asm volatile("atom.acq_rel.gpu.global.add.u32 %0, [%1], 1;"
                     : "=r"(t) : "l"(&g_ticket) : "memory");
        unsigned gen = t / NBLK_REC;
        if ((t % NBLK_REC) == NBLK_REC - 1) {
            asm volatile("st.release.gpu.global.u32 [%0], %1;"
                         :: "l"(&g_flag), "r"(gen + 1) : "memory");
        } else {
            unsigned target = gen + 1, cur;
            do {
                asm volatile("ld.acquire.gpu.global.u32 %0, [%1];"
                             : "=r"(cur) : "l"(&g_flag) : "memory");
            } while ((int)(cur - target) < 0);
        }
    }
    __syncthreads();
}

// ---------------- kernel 1: xg = emb[tokens] @ Wih^T + bih (fp32) ----------
// mode 1: encoder (token = toks[gm]); mode 2: decoder (SOS=1, then trg[:, :-1])
__global__ void __launch_bounds__(256) xg_gemm(
    const float* __restrict__ emb, const float* __restrict__ W,
    const float* __restrict__ bias, const int* __restrict__ toks,
    int T, int mode)
{
    float* out = (mode == 1) ? g_xg_enc : g_xg_dec;
    __shared__ __align__(16) float As[32][68];   // [k][m], pad 4
    __shared__ __align__(16) float Bs[32][68];   // [k][n], pad 4
    const int tid = threadIdx.x;
    const int m0 = blockIdx.y * 64;
    const int n0 = blockIdx.x * 64;
    const int tx = tid & 15, ty = tid >> 4;

    const float* arow[2];
    const float* brow[2];
    int rowi[2], qi[2];
#pragma unroll
    for (int i = 0; i < 2; i++) {
        int fid = tid + i * 256;
        int row = fid >> 3;
        rowi[i] = row;
        qi[i] = fid & 7;
        int gm = m0 + row;
        int tok;
        if (mode == 1) {
            tok = toks[gm];
        } else {
            int t = gm % T;
            int b = gm / T;
            tok = (t == 0) ? 1 : toks[b * T + t - 1];
        }
        arow[i] = emb + (long)tok * H_SZ;
        brow[i] = W + (long)(n0 + row) * H_SZ;
    }

    float acc[4][4];
#pragma unroll
    for (int i = 0; i < 4; i++)
#pragma unroll
        for (int j = 0; j < 4; j++) acc[i][j] = 0.f;

    for (int kc = 0; kc < H_SZ; kc += 32) {
        __syncthreads();
#pragma unroll
        for (int i = 0; i < 2; i++) {
            float4 av = *(const float4*)(arow[i] + kc + qi[i] * 4);
            float4 bv = *(const float4*)(brow[i] + kc + qi[i] * 4);
            int kb = qi[i] * 4, r = rowi[i];
            As[kb + 0][r] = av.x; As[kb + 1][r] = av.y;
            As[kb + 2][r] = av.z; As[kb + 3][r] = av.w;
            Bs[kb + 0][r] = bv.x; Bs[kb + 1][r] = bv.y;
            Bs[kb + 2][r] = bv.z; Bs[kb + 3][r] = bv.w;
        }
        __syncthreads();
#pragma unroll
        for (int kk = 0; kk < 32; kk++) {
            float4 a = *(const float4*)&As[kk][ty * 4];
            float4 b = *(const float4*)&Bs[kk][tx * 4];
            float av[4] = {a.x, a.y, a.z, a.w};
            float bv[4] = {b.x, b.y, b.z, b.w};
#pragma unroll
            for (int i = 0; i < 4; i++)
#pragma unroll
                for (int j = 0; j < 4; j++) acc[i][j] += av[i] * bv[j];
        }
    }

    float4 bb = *(const float4*)(bias + n0 + tx * 4);
    float bj[4] = {bb.x, bb.y, bb.z, bb.w};
#pragma unroll
    for (int i = 0; i < 4; i++) {
        int gm = m0 + ty * 4 + i;
        float4 o;
        o.x = acc[i][0] + bj[0]; o.y = acc[i][1] + bj[1];
        o.z = acc[i][2] + bj[2]; o.w = acc[i][3] + bj[3];
        *(float4*)(out + (long)gm * G_SZ + n0 + tx * 4) = o;
    }
}

// ---------------- kernel 2: persistent fused GRU recurrence ----------------
// 64 blocks x 256 threads; block owns 4 hidden channels (all 64 batches).
// Whh rows for both phases stay resident in smem for the whole kernel.
__global__ void __launch_bounds__(256) gru_rec(
    const float* __restrict__ encWhh, const float* __restrict__ encBhh,
    const float* __restrict__ decWhh, const float* __restrict__ decBhh)
{
    __shared__ __align__(16) float Whh_s[2][3][4][260];  // [phase][gate][cl][k]
    const int tid = threadIdx.x;
    const int blk = blockIdx.x;

    for (int idx = tid; idx < 6144; idx += 256) {
        int k  = idx & 255;
        int r  = idx >> 8;       // 0..23
        int cl = r & 3;
        int r2 = r >> 2;         // 0..5
        int g  = r2 % 3;
        int ph = r2 / 3;
        const float* srcW = ph ? decWhh : encWhh;
        Whh_s[ph][g][cl][k] = srcW[(long)(g * H_SZ + blk * 4 + cl) * H_SZ + k];
    }

    const int b  = tid >> 2;
    const int cl = tid & 3;
    const int c  = blk * 4 + cl;
    float bias_r[2] = {encBhh[c],            decBhh[c]};
    float bias_z[2] = {encBhh[H_SZ + c],     decBhh[H_SZ + c]};
    float bias_n[2] = {encBhh[2 * H_SZ + c], decBhh[2 * H_SZ + c]};

    g_h[0][b * H_SZ + c] = 0.f;   // zero initial hidden state
    __syncthreads();

    int cur = 0;
    for (int phase = 0; phase < 2; phase++) {
        const int T = phase ? T_DEC : T_ENC;
        const float* xg = phase ? g_xg_dec : g_xg_enc;
        const float br_ = bias_r[phase], bz_ = bias_z[phase], bn_ = bias_n[phase];
        for (int t = 0; t < T; t++) {
            grid_barrier();   // previous step's h writes visible (L2)
            const float* hrow = g_h[cur] + b * H_SZ;
            unsigned long long a_r0 = 0, a_r1 = 0, a_z0 = 0, a_z1 = 0, a_n0 = 0, a_n1 = 0;
#pragma unroll 4
            for (int k4 = 0; k4 < 64; k4++) {
                unsigned long long h0, h1;
                asm volatile("ld.global.cg.v2.u64 {%0,%1}, [%2];"
                             : "=l"(h0), "=l"(h1) : "l"(hrow + k4 * 4));
                const unsigned long long* wr =
                    (const unsigned long long*)&Whh_s[phase][0][cl][k4 * 4];
                const unsigned long long* wz =
                    (const unsigned long long*)&Whh_s[phase][1][cl][k4 * 4];
                const unsigned long long* wn =
                    (const unsigned long long*)&Whh_s[phase][2][cl][k4 * 4];
                fma2(a_r0, h0, wr[0]); fma2(a_r1, h1, wr[1]);
                fma2(a_z0, h0, wz[0]); fma2(a_z1, h1, wz[1]);
                fma2(a_n0, h0, wn[0]); fma2(a_n1, h1, wn[1]);
            }
            float gr = red2(a_r0, a_r1);
            float gz = red2(a_z0, a_z1);
            float gn = red2(a_n0, a_n1);

            float hold;
            asm volatile("ld.global.cg.f32 %0, [%1];"
                         : "=f"(hold) : "l"(g_h[cur] + b * H_SZ + c));

            const float* xp = xg + (long)(b * T + t) * G_SZ + c;
            float xr = __ldg(xp), xz = __ldg(xp + H_SZ), xn = __ldg(xp + 2 * H_SZ);

            float r = 1.f / (1.f + __expf(-(xr + gr + br_)));
            float z = 1.f / (1.f + __expf(-(xz + gz + bz_)));
            float n = tanhf(xn + r * (gn + bn_));
            float hnew = (1.f - z) * n + z * hold;

            float* ho = g_h[cur ^ 1] + b * H_SZ + c;
            asm volatile("st.global.cg.f32 [%0], %1;" :: "l"(ho), "f"(hnew));
            if (phase) g_dech[(long)(b * T_DEC + t) * H_SZ + c] = hnew;
            cur ^= 1;
        }
    }
}

// ---------------- kernel 3: logits = dec_h @ fc_W^T + fc_b (tf32 MMA) ------
// 128x128x32 block tile, 8 warps (2x4), warp tile 64x32, m16n8k8 tf32.
__global__ void __launch_bounds__(256) logits_gemm(
    const float* __restrict__ fcW, const float* __restrict__ fcb,
    float* __restrict__ out)
{
    __shared__ __align__(16) unsigned As[128][36];  // tf32 bits, [m][k], pad 4
    __shared__ __align__(16) unsigned Bs[128][36];  // tf32 bits, [n][k], pad 4
    const int tid = threadIdx.x;
    const int warp = tid >> 5, lane = tid & 31;
    const int group = lane >> 2, tig = lane & 3;
    const int m_blk = blockIdx.x * 128;
    const int n_blk = blockIdx.y * 128;
    const int m_w = (warp >> 2) * 64;
    const int n_w = (warp & 3) * 32;

    float acc[4][4][4];
#pragma unroll
    for (int i = 0; i < 4; i++)
#pragma unroll
        for (int j = 0; j < 4; j++)
#pragma unroll
            for (int k = 0; k < 4; k++) acc[i][j][k] = 0.f;

    for (int kc = 0; kc < 256; kc += 32) {
        __syncthreads();
#pragma unroll
        for (int i = 0; i < 4; i++) {
            int row = (tid >> 3) + i * 32;
            int q = tid & 7;
            float4 av = *(const float4*)(g_dech + (long)(m_blk + row) * 256 + kc + q * 4);
            float4 bv = *(const float4*)(fcW + (long)(n_blk + row) * 256 + kc + q * 4);
            uint4 ua, ub;
            ua.x = f2tf32(av.x); ua.y = f2tf32(av.y); ua.z = f2tf32(av.z); ua.w = f2tf32(av.w);
            ub.x = f2tf32(bv.x); ub.y = f2tf32(bv.y); ub.z = f2tf32(bv.z); ub.w = f2tf32(bv.w);
            *(uint4*)&As[row][q * 4] = ua;
            *(uint4*)&Bs[row][q * 4] = ub;
        }
        __syncthreads();
#pragma unroll
        for (int ks = 0; ks < 4; ks++) {
            const int k0 = ks * 8;
            unsigned a[4][4], bf[4][2];
#pragma unroll
            for (int mi = 0; mi < 4; mi++) {
                int r0 = m_w + mi * 16 + group;
                a[mi][0] = As[r0][k0 + tig];
                a[mi][1] = As[r0 + 8][k0 + tig];
                a[mi][2] = As[r0][k0 + tig + 4];
                a[mi][3] = As[r0 + 8][k0 + tig + 4];
            }
#pragma unroll
            for (int ni = 0; ni < 4; ni++) {
                int rn = n_w + ni * 8 + group;
                bf[ni][0] = Bs[rn][k0 + tig];
                bf[ni][1] = Bs[rn][k0 + tig + 4];
            }
#pragma unroll
            for (int mi = 0; mi < 4; mi++)
#pragma unroll
                for (int ni = 0; ni < 4; ni++)
                    mma_tf32(acc[mi][ni], a[mi], bf[ni][0], bf[ni][1]);
        }
    }

#pragma unroll
    for (int mi = 0; mi < 4; mi++) {
        int gm0 = m_blk + m_w + mi * 16 + group;
#pragma unroll
        for (int ni = 0; ni < 4; ni++) {
            int gn = n_blk + n_w + ni * 8 + tig * 2;
            float2 bb = *(const float2*)(fcb + gn);
            float2 o0, o1;
            o0.x = acc[mi][ni][0] + bb.x; o0.y = acc[mi][ni][1] + bb.y;
            o1.x = acc[mi][ni][2] + bb.x; o1.y = acc[mi][ni][3] + bb.y;
            *(float2*)(out + (long)gm0 * V_OUT + gn)       = o0;
            *(float2*)(out + (long)(gm0 + 8) * V_OUT + gn) = o1;
        }
    }
}

// ---------------- launch ----------------------------------------------------
extern "C" void kernel_launch(void* const* d_in, const int* in_sizes, int n_in,
                              void* d_out, int out_size) {
    const int*   src     = (const int*)  d_in[0];
    const int*   trg     = (const int*)  d_in[1];
    const float* enc_emb = (const float*)d_in[2];
    const float* enc_Wih = (const float*)d_in[3];
    const float* enc_Whh = (const float*)d_in[4];
    const float* enc_bih = (const float*)d_in[5];
    const float* enc_bhh = (const float*)d_in[6];
    const float* dec_emb = (const float*)d_in[7];
    const float* dec_Wih = (const float*)d_in[8];
    const float* dec_Whh = (const float*)d_in[9];
    const float* dec_bih = (const float*)d_in[10];
    const float* dec_bhh = (const float*)d_in[11];
    const float* fc_W    = (const float*)d_in[12];
    const float* fc_b    = (const float*)d_in[13];
    float* out = (float*)d_out;

    xg_gemm<<<dim3(G_SZ / 64, M_ENC / 64), 256>>>(enc_emb, enc_Wih, enc_bih, src, T_ENC, 1);
    xg_gemm<<<dim3(G_SZ / 64, M_DEC / 64), 256>>>(dec_emb, dec_Wih, dec_bih, trg, T_DEC, 2);
    gru_rec<<<NBLK_REC, 256>>>(enc_Whh, enc_bhh, dec_Whh, dec_bhh);
    logits_gemm<<<dim3(M_DEC / 128, V_OUT / 128), 256>>>(fc_W, fc_b, out);
}

// round 3
// speedup vs baseline: 1.4094x; 1.4094x over previous
#include <cuda_runtime.h>

#define B_SZ   64
#define H_SZ   256
#define G_SZ   768            // 3*H
#define T_ENC  48
#define T_DEC  32
#define V_OUT  32000
#define M_ENC  (B_SZ * T_ENC) // 3072
#define M_DEC  (B_SZ * T_DEC) // 2048

// gru cluster config: 16 clusters x 8 CTAs, 4 batches per cluster, 32 ch per CTA
#define GR_RANKS 8
#define GR_BPC   4
#define GR_CTAS  128

// smem layout (floats) for gru_rec
#define WS_FLOATS  (6 * 32 * 257)            // 49344: [gt][ch][k pad257]
#define HS_OFF     WS_FLOATS                 // [2][256][4]
#define HS_FLOATS  (2 * 256 * 4)
#define RED_OFF    (HS_OFF + HS_FLOATS)      // [32][97]
#define RED_FLOATS (32 * 97)
#define GR_SMEM_BYTES ((WS_FLOATS + HS_FLOATS + RED_FLOATS) * 4)

// ---------------- device scratch (static, no runtime allocation) ----------
__device__ float g_xg_enc[M_ENC * G_SZ];   // [b*48+t][768]
__device__ float g_xg_dec[M_DEC * G_SZ];   // [b*32+t][768]
__device__ float g_dech[M_DEC * H_SZ];     // decoder hidden outputs

// ---------------- helpers --------------------------------------------------
__device__ __forceinline__ unsigned f2tf32(float x) {
    unsigned r; asm("cvt.rna.tf32.f32 %0, %1;" : "=r"(r) : "f"(x)); return r;
}

__device__ __forceinline__ void mma_tf32(float* d, const unsigned* a,
                                         unsigned b0, unsigned b1) {
    asm volatile(
        "mma.sync.aligned.m16n8k8.row.col.f32.tf32.tf32.f32 "
        "{%0,%1,%2,%3}, {%4,%5,%6,%7}, {%8,%9}, {%0,%1,%2,%3};"
        : "+f"(d[0]), "+f"(d[1]), "+f"(d[2]), "+f"(d[3])
        : "r"(a[0]), "r"(a[1]), "r"(a[2]), "r"(a[3]), "r"(b0), "r"(b1));
}

__device__ __forceinline__ void fma2(unsigned long long& d,
                                     unsigned long long a, unsigned long long b) {
    asm("fma.rn.f32x2 %0, %1, %2, %0;" : "+l"(d) : "l"(a), "l"(b));
}

__device__ __forceinline__ void unpack2(unsigned long long v, float& lo, float& hi) {
    asm("mov.b64 {%0,%1}, %2;" : "=f"(lo), "=f"(hi) : "l"(v));
}

__device__ __forceinline__ unsigned long long dup2(float w) {
    unsigned long long d;
    asm("mov.b64 %0, {%1,%1};" : "=l"(d) : "f"(w));
    return d;
}

__device__ __forceinline__ unsigned smem_u32(const void* p) {
    unsigned a;
    asm("{ .reg .u64 t; cvta.to.shared.u64 t, %1; cvt.u32.u64 %0, t; }"
        : "=r"(a) : "l"(p));
    return a;
}

// ---------------- kernel 1: xg = emb[tokens] @ Wih^T + bih (fp32) ----------
// mode 1: encoder (token = toks[gm]); mode 2: decoder (SOS=1, then trg[:, :-1])
__global__ void __launch_bounds__(256) xg_gemm(
    const float* __restrict__ emb, const float* __restrict__ W,
    const float* __restrict__ bias, const int* __restrict__ toks,
    int T, int mode)
{
    float* out = (mode == 1) ? g_xg_enc : g_xg_dec;
    __shared__ __align__(16) float As[32][68];   // [k][m], pad 4
    __shared__ __align__(16) float Bs[32][68];   // [k][n], pad 4
    const int tid = threadIdx.x;
    const int m0 = blockIdx.y * 64;
    const int n0 = blockIdx.x * 64;
    const int tx = tid & 15, ty = tid >> 4;

    const float* arow[2];
    const float* brow[2];
    int rowi[2], qi[2];
#pragma unroll
    for (int i = 0; i < 2; i++) {
        int fid = tid + i * 256;
        int row = fid >> 3;
        rowi[i] = row;
        qi[i] = fid & 7;
        int gm = m0 + row;
        int tok;
        if (mode == 1) {
            tok = toks[gm];
        } else {
            int t = gm % T;
            int b = gm / T;
            tok = (t == 0) ? 1 : toks[b * T + t - 1];
        }
        arow[i] = emb + (long)tok * H_SZ;
        brow[i] = W + (long)(n0 + row) * H_SZ;
    }

    float acc[4][4];
#pragma unroll
    for (int i = 0; i < 4; i++)
#pragma unroll
        for (int j = 0; j < 4; j++) acc[i][j] = 0.f;

    for (int kc = 0; kc < H_SZ; kc += 32) {
        __syncthreads();
#pragma unroll
        for (int i = 0; i < 2; i++) {
            float4 av = *(const float4*)(arow[i] + kc + qi[i] * 4);
            float4 bv = *(const float4*)(brow[i] + kc + qi[i] * 4);
            int kb = qi[i] * 4, r = rowi[i];
            As[kb + 0][r] = av.x; As[kb + 1][r] = av.y;
            As[kb + 2][r] = av.z; As[kb + 3][r] = av.w;
            Bs[kb + 0][r] = bv.x; Bs[kb + 1][r] = bv.y;
            Bs[kb + 2][r] = bv.z; Bs[kb + 3][r] = bv.w;
        }
        __syncthreads();
#pragma unroll
        for (int kk = 0; kk < 32; kk++) {
            float4 a = *(const float4*)&As[kk][ty * 4];
            float4 b = *(const float4*)&Bs[kk][tx * 4];
            float av[4] = {a.x, a.y, a.z, a.w};
            float bv[4] = {b.x, b.y, b.z, b.w};
#pragma unroll
            for (int i = 0; i < 4; i++)
#pragma unroll
                for (int j = 0; j < 4; j++) acc[i][j] += av[i] * bv[j];
        }
    }

    float4 bb = *(const float4*)(bias + n0 + tx * 4);
    float bj[4] = {bb.x, bb.y, bb.z, bb.w};
#pragma unroll
    for (int i = 0; i < 4; i++) {
        int gm = m0 + ty * 4 + i;
        float4 o;
        o.x = acc[i][0] + bj[0]; o.y = acc[i][1] + bj[1];
        o.z = acc[i][2] + bj[2]; o.w = acc[i][3] + bj[3];
        *(float4*)(out + (long)gm * G_SZ + n0 + tx * 4) = o;
    }
}

// ---------------- kernel 2: cluster-parallel GRU recurrence ----------------
// 16 clusters of 8 CTAs. Cluster c owns batches [4c, 4c+4). CTA rank r owns
// hidden channels [32r, 32r+32): its 96 Whh rows (both phases) live in smem
// for the whole kernel. h (replicated per CTA, double-buffered, [k][batch]
// layout) is exchanged via DSMEM stores + cluster.sync each step.
__global__ void __launch_bounds__(256)
__cluster_dims__(GR_RANKS, 1, 1)
gru_rec(const float* __restrict__ encWhh, const float* __restrict__ encBhh,
        const float* __restrict__ decWhh, const float* __restrict__ decBhh)
{
    extern __shared__ __align__(16) float sm[];
    float* w_s  = sm;            // [6][32][257]
    float* h_s  = sm + HS_OFF;   // [2][256][4]  (k-major, batch minor)
    float* redm = sm + RED_OFF;  // [32][97]

    const int tid  = threadIdx.x;
    const int j    = tid & 31;   // channel within CTA (dot role)
    const int ksl  = tid >> 5;   // k-slice warp: k in [32*ksl, 32*ksl+32)
    const int rank = blockIdx.x & (GR_RANKS - 1);
    const int cid  = blockIdx.x >> 3;

    // ---- load both phases' Whh slices into smem (row pad 257 -> CF) ----
    for (int fid = tid; fid < 6 * 32 * 64; fid += 256) {
        int q  = fid & 63;           // float4 index within row
        int rl = fid >> 6;           // 0..191
        int gt = rl >> 5;            // 0..5  (phase*3 + gate)
        int ch = rl & 31;
        const float* W = (gt >= 3) ? decWhh : encWhh;
        int g = (gt >= 3) ? gt - 3 : gt;
        float4 v = *(const float4*)(W + (long)(g * H_SZ + rank * 32 + ch) * H_SZ + q * 4);
        float* dst = w_s + (gt * 32 + ch) * 257 + q * 4;
        dst[0] = v.x; dst[1] = v.y; dst[2] = v.z; dst[3] = v.w;
    }
    // ---- zero initial hidden state (buffer 0) ----
    for (int i = tid; i < 1024; i += 256) h_s[i] = 0.f;
    __syncthreads();

    // reducer role: threads 0..127 -> (batch b_r = tid>>5, channel ch_r = tid&31)
    const bool is_red = (tid < 128);
    const int ch_r = tid & 31;
    const int b_r  = tid >> 5;
    const int cg   = rank * 32 + ch_r;      // global channel
    const int bg   = cid * GR_BPC + b_r;    // global batch

    const unsigned h_base = smem_u32(h_s);

    int buf = 0;
    for (int ph = 0; ph < 2; ph++) {
        const int T = ph ? T_DEC : T_ENC;
        const float* xg  = ph ? g_xg_dec : g_xg_enc;
        const float* Bhh = ph ? decBhh : encBhh;
        float br = 0.f, bz = 0.f, bn = 0.f;
        if (is_red) {
            br = __ldg(Bhh + cg);
            bz = __ldg(Bhh + H_SZ + cg);
            bn = __ldg(Bhh + 2 * H_SZ + cg);
        }
        const float* w0 = w_s + ((ph * 3 + 0) * 32 + j) * 257 + ksl * 32;
        const float* w1 = w_s + ((ph * 3 + 1) * 32 + j) * 257 + ksl * 32;
        const float* w2 = w_s + ((ph * 3 + 2) * 32 + j) * 257 + ksl * 32;

        for (int t = 0; t < T; t++) {
            // prefetch xg early (latency hidden under the dot products)
            float xr = 0.f, xz = 0.f, xn = 0.f;
            if (is_red) {
                const float* xp = xg + (long)(bg * T + t) * G_SZ + cg;
                xr = __ldg(xp); xz = __ldg(xp + H_SZ); xn = __ldg(xp + 2 * H_SZ);
            }

            // ---- partial dot products over this warp's k-slice ----
            unsigned long long a01[3] = {0ull, 0ull, 0ull};  // batches (0,1)
            unsigned long long a23[3] = {0ull, 0ull, 0ull};  // batches (2,3)
            const float* hb = h_s + buf * 1024 + ksl * 128;  // [k][4], k-slice
#pragma unroll 8
            for (int kk = 0; kk < 32; kk++) {
                ulonglong2 hv = *(const ulonglong2*)(hb + kk * 4);
                unsigned long long wd;
                wd = dup2(w0[kk]); fma2(a01[0], hv.x, wd); fma2(a23[0], hv.y, wd);
                wd = dup2(w1[kk]); fma2(a01[1], hv.x, wd); fma2(a23[1], hv.y, wd);
                wd = dup2(w2[kk]); fma2(a01[2], hv.x, wd); fma2(a23[2], hv.y, wd);
            }
            // ---- stash partials: red[ch][g*32 + b*8 + ksl] ----
#pragma unroll
            for (int g = 0; g < 3; g++) {
                float p0, p1, p2, p3;
                unpack2(a01[g], p0, p1);
                unpack2(a23[g], p2, p3);
                float* rp = redm + j * 97 + g * 32 + ksl;
                rp[0]  = p0; rp[8]  = p1;
                rp[16] = p2; rp[24] = p3;
            }
            __syncthreads();

            // ---- reduce + gate nonlinearity + DSMEM broadcast ----
            if (is_red) {
                float s[3];
#pragma unroll
                for (int g = 0; g < 3; g++) {
                    const float* rp = redm + ch_r * 97 + g * 32 + b_r * 8;
                    s[g] = ((rp[0] + rp[1]) + (rp[2] + rp[3]))
                         + ((rp[4] + rp[5]) + (rp[6] + rp[7]));
                }
                float hold = h_s[buf * 1024 + cg * 4 + b_r];
                float r = 1.f / (1.f + __expf(-(xr + s[0] + br)));
                float z = 1.f / (1.f + __expf(-(xz + s[1] + bz)));
                float n = tanhf(xn + r * (s[2] + bn));
                float hnew = (1.f - z) * n + z * hold;

                unsigned laddr = h_base + (unsigned)(((buf ^ 1) * 1024 + cg * 4 + b_r) * 4);
#pragma unroll
                for (int rr = 0; rr < GR_RANKS; rr++) {
                    unsigned ra;
                    asm volatile("mapa.shared::cluster.u32 %0, %1, %2;"
                                 : "=r"(ra) : "r"(laddr), "r"(rr));
                    asm volatile("st.shared::cluster.f32 [%0], %1;"
                                 :: "r"(ra), "f"(hnew) : "memory");
                }
                if (ph) g_dech[(long)(bg * T_DEC + t) * H_SZ + cg] = hnew;
            }
            // one cluster barrier per step (also a CTA-wide barrier)
            asm volatile("barrier.cluster.arrive.aligned;" ::: "memory");
            asm volatile("barrier.cluster.wait.aligned;" ::: "memory");
            buf ^= 1;
        }
    }
}

// ---------------- kernel 3: logits = dec_h @ fc_W^T + fc_b (tf32 MMA) ------
// 128x128x32 block tile, 8 warps (2x4), warp tile 64x32, m16n8k8 tf32.
__global__ void __launch_bounds__(256) logits_gemm(
    const float* __restrict__ fcW, const float* __restrict__ fcb,
    float* __restrict__ out)
{
    __shared__ __align__(16) unsigned As[128][36];  // tf32 bits, [m][k], pad 4
    __shared__ __align__(16) unsigned Bs[128][36];  // tf32 bits, [n][k], pad 4
    const int tid = threadIdx.x;
    const int warp = tid >> 5, lane = tid & 31;
    const int group = lane >> 2, tig = lane & 3;
    const int m_blk = blockIdx.x * 128;
    const int n_blk = blockIdx.y * 128;
    const int m_w = (warp >> 2) * 64;
    const int n_w = (warp & 3) * 32;

    float acc[4][4][4];
#pragma unroll
    for (int i = 0; i < 4; i++)
#pragma unroll
        for (int j = 0; j < 4; j++)
#pragma unroll
            for (int k = 0; k < 4; k++) acc[i][j][k] = 0.f;

    for (int kc = 0; kc < 256; kc += 32) {
        __syncthreads();
#pragma unroll
        for (int i = 0; i < 4; i++) {
            int row = (tid >> 3) + i * 32;
            int q = tid & 7;
            float4 av = *(const float4*)(g_dech + (long)(m_blk + row) * 256 + kc + q * 4);
            float4 bv = *(const float4*)(fcW + (long)(n_blk + row) * 256 + kc + q * 4);
            uint4 ua, ub;
            ua.x = f2tf32(av.x); ua.y = f2tf32(av.y); ua.z = f2tf32(av.z); ua.w = f2tf32(av.w);
            ub.x = f2tf32(bv.x); ub.y = f2tf32(bv.y); ub.z = f2tf32(bv.z); ub.w = f2tf32(bv.w);
            *(uint4*)&As[row][q * 4] = ua;
            *(uint4*)&Bs[row][q * 4] = ub;
        }
        __syncthreads();
#pragma unroll
        for (int ks = 0; ks < 4; ks++) {
            const int k0 = ks * 8;
            unsigned a[4][4], bf[4][2];
#pragma unroll
            for (int mi = 0; mi < 4; mi++) {
                int r0 = m_w + mi * 16 + group;
                a[mi][0] = As[r0][k0 + tig];
                a[mi][1] = As[r0 + 8][k0 + tig];
                a[mi][2] = As[r0][k0 + tig + 4];
                a[mi][3] = As[r0 + 8][k0 + tig + 4];
            }
#pragma unroll
            for (int ni = 0; ni < 4; ni++) {
                int rn = n_w + ni * 8 + group;
                bf[ni][0] = Bs[rn][k0 + tig];
                bf[ni][1] = Bs[rn][k0 + tig + 4];
            }
#pragma unroll
            for (int mi = 0; mi < 4; mi++)
#pragma unroll
                for (int ni = 0; ni < 4; ni++)
                    mma_tf32(acc[mi][ni], a[mi], bf[ni][0], bf[ni][1]);
        }
    }

#pragma unroll
    for (int mi = 0; mi < 4; mi++) {
        int gm0 = m_blk + m_w + mi * 16 + group;
#pragma unroll
        for (int ni = 0; ni < 4; ni++) {
            int gn = n_blk + n_w + ni * 8 + tig * 2;
            float2 bb = *(const float2*)(fcb + gn);
            float2 o0, o1;
            o0.x = acc[mi][ni][0] + bb.x; o0.y = acc[mi][ni][1] + bb.y;
            o1.x = acc[mi][ni][2] + bb.x; o1.y = acc[mi][ni][3] + bb.y;
            *(float2*)(out + (long)gm0 * V_OUT + gn)       = o0;
            *(float2*)(out + (long)(gm0 + 8) * V_OUT + gn) = o1;
        }
    }
}

// ---------------- launch ----------------------------------------------------
extern "C" void kernel_launch(void* const* d_in, const int* in_sizes, int n_in,
                              void* d_out, int out_size) {
    const int*   src     = (const int*)  d_in[0];
    const int*   trg     = (const int*)  d_in[1];
    const float* enc_emb = (const float*)d_in[2];
    const float* enc_Wih = (const float*)d_in[3];
    const float* enc_Whh = (const float*)d_in[4];
    const float* enc_bih = (const float*)d_in[5];
    const float* enc_bhh = (const float*)d_in[6];
    const float* dec_emb = (const float*)d_in[7];
    const float* dec_Wih = (const float*)d_in[8];
    const float* dec_Whh = (const float*)d_in[9];
    const float* dec_bih = (const float*)d_in[10];
    const float* dec_bhh = (const float*)d_in[11];
    const float* fc_W    = (const float*)d_in[12];
    const float* fc_b    = (const float*)d_in[13];
    float* out = (float*)d_out;

    static bool attr_done = false;
    if (!attr_done) {
        cudaFuncSetAttribute((const void*)gru_rec,
                             cudaFuncAttributeMaxDynamicSharedMemorySize,
                             GR_SMEM_BYTES);
        attr_done = true;
    }

    xg_gemm<<<dim3(G_SZ / 64, M_ENC / 64), 256>>>(enc_emb, enc_Wih, enc_bih, src, T_ENC, 1);
    xg_gemm<<<dim3(G_SZ / 64, M_DEC / 64), 256>>>(dec_emb, dec_Wih, dec_bih, trg, T_DEC, 2);
    gru_rec<<<GR_CTAS, 256, GR_SMEM_BYTES>>>(enc_Whh, enc_bhh, dec_Whh, dec_bhh);
    logits_gemm<<<dim3(M_DEC / 128, V_OUT / 128), 256>>>(fc_W, fc_b, out);
}

// round 5
// speedup vs baseline: 1.5575x; 1.1050x over previous
#include <cuda_runtime.h>
#include <cstdint>

#define B_SZ   64
#define H_SZ   256
#define G_SZ   768            // 3*H
#define T_ENC  48
#define T_DEC  32
#define V_OUT  32000
#define M_ENC  (B_SZ * T_ENC) // 3072
#define M_DEC  (B_SZ * T_DEC) // 2048

// gru cluster config: 16 clusters x 8 CTAs, 4 batches per cluster, 32 ch per CTA
#define GR_RANKS 8
#define GR_BPC   4
#define GR_CTAS  128

// smem layout (floats) for gru_rec
#define WS_FLOATS  (6 * 32 * 257)            // [gt][ch][k pad257]
#define HS_OFF     WS_FLOATS                 // [2][256][4]
#define HS_FLOATS  (2 * 256 * 4)
#define RED_OFF    (HS_OFF + HS_FLOATS)      // [32][97]
#define RED_FLOATS (32 * 97)
#define GR_SMEM_BYTES ((WS_FLOATS + HS_FLOATS + RED_FLOATS) * 4)

// logits config: Tm=256, Tn=128, k-chunk 32, fp16 mma, double buffered
#define LG_AB_UINTS 4096      // 256 rows x 16 half2
#define LG_BB_UINTS 2048      // 128 rows x 16 half2
#define LG_BUF_UINTS (LG_AB_UINTS + LG_BB_UINTS)   // 6144
#define LG_SMEM_BYTES (2 * LG_BUF_UINTS * 4)       // 49152

// ---------------- device scratch (static, no runtime allocation) ----------
__device__ float g_xg_enc[M_ENC * G_SZ];   // [b*48+t][768]
__device__ float g_xg_dec[M_DEC * G_SZ];   // [b*32+t][768]
__device__ float g_dech[M_DEC * H_SZ];     // decoder hidden outputs

// ---------------- helpers --------------------------------------------------
__device__ __forceinline__ void fma2(unsigned long long& d,
                                     unsigned long long a, unsigned long long b) {
    asm("fma.rn.f32x2 %0, %1, %2, %0;" : "+l"(d) : "l"(a), "l"(b));
}

__device__ __forceinline__ void unpack2(unsigned long long v, float& lo, float& hi) {
    asm("mov.b64 {%0,%1}, %2;" : "=f"(lo), "=f"(hi) : "l"(v));
}

__device__ __forceinline__ unsigned long long dup2(float w) {
    unsigned long long d;
    asm("mov.b64 %0, {%1,%1};" : "=l"(d) : "f"(w));
    return d;
}

__device__ __forceinline__ unsigned smem_u32(const void* p) {
    unsigned a;
    asm("{ .reg .u64 t; cvta.to.shared.u64 t, %1; cvt.u32.u64 %0, t; }"
        : "=r"(a) : "l"(p));
    return a;
}

// pack two fp32 into half2 (lo = first arg)
__device__ __forceinline__ unsigned pack_h2(float lo, float hi) {
    unsigned r;
    asm("cvt.rn.f16x2.f32 %0, %1, %2;" : "=r"(r) : "f"(hi), "f"(lo));
    return r;
}

__device__ __forceinline__ void mma_f16(float* d,
                                        unsigned a0, unsigned a1, unsigned a2, unsigned a3,
                                        unsigned b0, unsigned b1) {
    asm volatile(
        "mma.sync.aligned.m16n8k16.row.col.f32.f16.f16.f32 "
        "{%0,%1,%2,%3}, {%4,%5,%6,%7}, {%8,%9}, {%0,%1,%2,%3};"
        : "+f"(d[0]), "+f"(d[1]), "+f"(d[2]), "+f"(d[3])
        : "r"(a0), "r"(a1), "r"(a2), "r"(a3), "r"(b0), "r"(b1));
}

// ---------------- kernel 1: xg = emb[tokens] @ Wih^T + bih (fp32) ----------
// single launch covers encoder (gridY < 48) and decoder (gridY >= 48)
__global__ void __launch_bounds__(256) xg_gemm_all(
    const float* __restrict__ enc_emb, const float* __restrict__ enc_Wih,
    const float* __restrict__ enc_bih, const int* __restrict__ src,
    const float* __restrict__ dec_emb, const float* __restrict__ dec_Wih,
    const float* __restrict__ dec_bih, const int* __restrict__ trg)
{
    const int by = blockIdx.y;
    const bool enc = (by < 48);
    const float* emb  = enc ? enc_emb : dec_emb;
    const float* W    = enc ? enc_Wih : dec_Wih;
    const float* bias = enc ? enc_bih : dec_bih;
    float* out        = enc ? g_xg_enc : g_xg_dec;
    const int T       = enc ? T_ENC : T_DEC;
    const int m0      = (enc ? by : by - 48) * 64;

    __shared__ __align__(16) float As[32][68];
    __shared__ __align__(16) float Bs[32][68];
    const int tid = threadIdx.x;
    const int n0 = blockIdx.x * 64;
    const int tx = tid & 15, ty = tid >> 4;

    const float* arow[2];
    const float* brow[2];
    int rowi[2], qi[2];
#pragma unroll
    for (int i = 0; i < 2; i++) {
        int fid = tid + i * 256;
        int row = fid >> 3;
        rowi[i] = row;
        qi[i] = fid & 7;
        int gm = m0 + row;
        int tok;
        if (enc) {
            tok = src[gm];
        } else {
            int t = gm % T;
            int b = gm / T;
            tok = (t == 0) ? 1 : trg[b * T + t - 1];
        }
        arow[i] = emb + (long)tok * H_SZ;
        brow[i] = W + (long)(n0 + row) * H_SZ;
    }

    float acc[4][4];
#pragma unroll
    for (int i = 0; i < 4; i++)
#pragma unroll
        for (int j = 0; j < 4; j++) acc[i][j] = 0.f;

    for (int kc = 0; kc < H_SZ; kc += 32) {
        __syncthreads();
#pragma unroll
        for (int i = 0; i < 2; i++) {
            float4 av = *(const float4*)(arow[i] + kc + qi[i] * 4);
            float4 bv = *(const float4*)(brow[i] + kc + qi[i] * 4);
            int kb = qi[i] * 4, r = rowi[i];
            As[kb + 0][r] = av.x; As[kb + 1][r] = av.y;
            As[kb + 2][r] = av.z; As[kb + 3][r] = av.w;
            Bs[kb + 0][r] = bv.x; Bs[kb + 1][r] = bv.y;
            Bs[kb + 2][r] = bv.z; Bs[kb + 3][r] = bv.w;
        }
        __syncthreads();
#pragma unroll
        for (int kk = 0; kk < 32; kk++) {
            float4 a = *(const float4*)&As[kk][ty * 4];
            float4 b = *(const float4*)&Bs[kk][tx * 4];
            float av[4] = {a.x, a.y, a.z, a.w};
            float bv[4] = {b.x, b.y, b.z, b.w};
#pragma unroll
            for (int i = 0; i < 4; i++)
#pragma unroll
                for (int j = 0; j < 4; j++) acc[i][j] += av[i] * bv[j];
        }
    }

    float4 bb = *(const float4*)(bias + n0 + tx * 4);
    float bj[4] = {bb.x, bb.y, bb.z, bb.w};
#pragma unroll
    for (int i = 0; i < 4; i++) {
        int gm = m0 + ty * 4 + i;
        float4 o;
        o.x = acc[i][0] + bj[0]; o.y = acc[i][1] + bj[1];
        o.z = acc[i][2] + bj[2]; o.w = acc[i][3] + bj[3];
        *(float4*)(out + (long)gm * G_SZ + n0 + tx * 4) = o;
    }
}

// ---------------- kernel 2: cluster-parallel GRU recurrence ----------------
__global__ void __launch_bounds__(256)
__cluster_dims__(GR_RANKS, 1, 1)
gru_rec(const float* __restrict__ encWhh, const float* __restrict__ encBhh,
        const float* __restrict__ decWhh, const float* __restrict__ decBhh)
{
    extern __shared__ __align__(16) float sm[];
    float* w_s  = sm;            // [6][32][257]
    float* h_s  = sm + HS_OFF;   // [2][256][4]  (k-major, batch minor)
    float* redm = sm + RED_OFF;  // [32][97]

    const int tid  = threadIdx.x;
    const int j    = tid & 31;
    const int ksl  = tid >> 5;
    const int rank = blockIdx.x & (GR_RANKS - 1);
    const int cid  = blockIdx.x >> 3;

    for (int fid = tid; fid < 6 * 32 * 64; fid += 256) {
        int q  = fid & 63;
        int rl = fid >> 6;
        int gt = rl >> 5;
        int ch = rl & 31;
        const float* W = (gt >= 3) ? decWhh : encWhh;
        int g = (gt >= 3) ? gt - 3 : gt;
        float4 v = *(const float4*)(W + (long)(g * H_SZ + rank * 32 + ch) * H_SZ + q * 4);
        float* dst = w_s + (gt * 32 + ch) * 257 + q * 4;
        dst[0] = v.x; dst[1] = v.y; dst[2] = v.z; dst[3] = v.w;
    }
    for (int i = tid; i < 1024; i += 256) h_s[i] = 0.f;
    __syncthreads();

    const bool is_red = (tid < 128);
    const int ch_r = tid & 31;
    const int b_r  = tid >> 5;
    const int cg   = rank * 32 + ch_r;
    const int bg   = cid * GR_BPC + b_r;

    const unsigned h_base = smem_u32(h_s);

    int buf = 0;
    for (int ph = 0; ph < 2; ph++) {
        const int T = ph ? T_DEC : T_ENC;
        const float* xg  = ph ? g_xg_dec : g_xg_enc;
        const float* Bhh = ph ? decBhh : encBhh;
        float br = 0.f, bz = 0.f, bn = 0.f;
        if (is_red) {
            br = __ldg(Bhh + cg);
            bz = __ldg(Bhh + H_SZ + cg);
            bn = __ldg(Bhh + 2 * H_SZ + cg);
        }
        const float* w0 = w_s + ((ph * 3 + 0) * 32 + j) * 257 + ksl * 32;
        const float* w1 = w_s + ((ph * 3 + 1) * 32 + j) * 257 + ksl * 32;
        const float* w2 = w_s + ((ph * 3 + 2) * 32 + j) * 257 + ksl * 32;

        for (int t = 0; t < T; t++) {
            float xr = 0.f, xz = 0.f, xn = 0.f;
            if (is_red) {
                const float* xp = xg + (long)(bg * T + t) * G_SZ + cg;
                xr = __ldg(xp); xz = __ldg(xp + H_SZ); xn = __ldg(xp + 2 * H_SZ);
            }

            unsigned long long a01[3] = {0ull, 0ull, 0ull};
            unsigned long long a23[3] = {0ull, 0ull, 0ull};
            const float* hb = h_s + buf * 1024 + ksl * 128;
#pragma unroll 8
            for (int kk = 0; kk < 32; kk++) {
                ulonglong2 hv = *(const ulonglong2*)(hb + kk * 4);
                unsigned long long wd;
                wd = dup2(w0[kk]); fma2(a01[0], hv.x, wd); fma2(a23[0], hv.y, wd);
                wd = dup2(w1[kk]); fma2(a01[1], hv.x, wd); fma2(a23[1], hv.y, wd);
                wd = dup2(w2[kk]); fma2(a01[2], hv.x, wd); fma2(a23[2], hv.y, wd);
            }
#pragma unroll
            for (int g = 0; g < 3; g++) {
                float p0, p1, p2, p3;
                unpack2(a01[g], p0, p1);
                unpack2(a23[g], p2, p3);
                float* rp = redm + j * 97 + g * 32 + ksl;
                rp[0]  = p0; rp[8]  = p1;
                rp[16] = p2; rp[24] = p3;
            }
            __syncthreads();

            if (is_red) {
                float s[3];
#pragma unroll
                for (int g = 0; g < 3; g++) {
                    const float* rp = redm + ch_r * 97 + g * 32 + b_r * 8;
                    s[g] = ((rp[0] + rp[1]) + (rp[2] + rp[3]))
                         + ((rp[4] + rp[5]) + (rp[6] + rp[7]));
                }
                float hold = h_s[buf * 1024 + cg * 4 + b_r];
                float r = 1.f / (1.f + __expf(-(xr + s[0] + br)));
                float z = 1.f / (1.f + __expf(-(xz + s[1] + bz)));
                float n = tanhf(xn + r * (s[2] + bn));
                float hnew = (1.f - z) * n + z * hold;

                unsigned laddr = h_base + (unsigned)(((buf ^ 1) * 1024 + cg * 4 + b_r) * 4);
#pragma unroll
                for (int rr = 0; rr < GR_RANKS; rr++) {
                    unsigned ra;
                    asm volatile("mapa.shared::cluster.u32 %0, %1, %2;"
                                 : "=r"(ra) : "r"(laddr), "r"(rr));
                    asm volatile("st.shared::cluster.f32 [%0], %1;"
                                 :: "r"(ra), "f"(hnew) : "memory");
                }
                if (ph) g_dech[(long)(bg * T_DEC + t) * H_SZ + cg] = hnew;
            }
            asm volatile("barrier.cluster.arrive.aligned;" ::: "memory");
            asm volatile("barrier.cluster.wait.aligned;" ::: "memory");
            buf ^= 1;
        }
    }
}

// ---------------- kernel 3: logits = dec_h @ fc_W^T + fc_b (fp16 MMA) ------
// Tile 256x128, 8 warps (warp 64x64), k-chunk 32, double-buffered fp16 smem,
// LDG prefetch overlapped with mma. Permuted half2 layout: h2-column c' =
// (h2&3)*4 + (h2>>2), XOR-swizzled by ((row>>1)&1) at uint2 granularity so
// frag loads are single conflict-free LDS.64 per row.
__global__ void __launch_bounds__(256) logits_f16(
    const float* __restrict__ fcW, const float* __restrict__ fcb,
    float* __restrict__ out)
{
    extern __shared__ __align__(16) unsigned smu[];
    const int tid = threadIdx.x;
    const int warp = tid >> 5, lane = tid & 31;
    const int group = lane >> 2, tig = lane & 3;
    const int m_blk = blockIdx.x * 256;
    const int n_blk = blockIdx.y * 128;
    const int m_w = (warp >> 1) * 64;
    const int n_w = (warp & 1) * 64;

    float acc[4][8][4];
#pragma unroll
    for (int i = 0; i < 4; i++)
#pragma unroll
        for (int j = 0; j < 8; j++)
#pragma unroll
            for (int k = 0; k < 4; k++) acc[i][j][k] = 0.f;

    float4 va[8], vb[4];

    // prefetch regs for chunk kc (A rows 256, B rows 128, 32 k each)
#define LG_LOAD(kc_) do {                                                     \
    _Pragma("unroll")                                                         \
    for (int i = 0; i < 8; i++) {                                             \
        int f = i * 256 + tid; int row = f >> 3; int q = f & 7;               \
        va[i] = *(const float4*)(g_dech + (long)(m_blk + row) * 256 + (kc_) + q * 4); \
    }                                                                         \
    _Pragma("unroll")                                                         \
    for (int i = 0; i < 4; i++) {                                             \
        int f = i * 256 + tid; int row = f >> 3; int q = f & 7;               \
        vb[i] = *(const float4*)(fcW + (long)(n_blk + row) * 256 + (kc_) + q * 4); \
    }                                                                         \
} while (0)

#define LG_STS(bufu) do {                                                     \
    unsigned* ab = (bufu);                                                    \
    unsigned* bb2 = (bufu) + LG_AB_UINTS;                                     \
    _Pragma("unroll")                                                         \
    for (int i = 0; i < 8; i++) {                                             \
        int f = i * 256 + tid; int row = f >> 3; int q = f & 7;               \
        int h2a = 2 * q, h2b = 2 * q + 1;                                     \
        int ca = ((h2a & 3) << 2) | (h2a >> 2);                               \
        int cb = ((h2b & 3) << 2) | (h2b >> 2);                               \
        int sw = ((row >> 1) & 1) << 1;                                       \
        ab[row * 16 + (ca ^ sw)] = pack_h2(va[i].x, va[i].y);                 \
        ab[row * 16 + (cb ^ sw)] = pack_h2(va[i].z, va[i].w);                 \
    }                                                                         \
    _Pragma("unroll")                                                         \
    for (int i = 0; i < 4; i++) {                                             \
        int f = i * 256 + tid; int row = f >> 3; int q = f & 7;               \
        int h2a = 2 * q, h2b = 2 * q + 1;                                     \
        int ca = ((h2a & 3) << 2) | (h2a >> 2);                               \
        int cb = ((h2b & 3) << 2) | (h2b >> 2);                               \
        int sw = ((row >> 1) & 1) << 1;                                       \
        bb2[row * 16 + (ca ^ sw)] = pack_h2(vb[i].x, vb[i].y);                \
        bb2[row * 16 + (cb ^ sw)] = pack_h2(vb[i].z, vb[i].w);                \
    }                                                                         \
} while (0)

    // prologue: chunk 0
    LG_LOAD(0);
    LG_STS(smu);
    __syncthreads();

    for (int c = 0; c < 8; c++) {
        unsigned* cur = smu + (c & 1) * LG_BUF_UINTS;
        if (c < 7) LG_LOAD((c + 1) * 32);     // LDGs in flight under the mmas

        const unsigned* ab = cur;
        const unsigned* bb2 = cur + LG_AB_UINTS;
#pragma unroll
        for (int s = 0; s < 2; s++) {
            uint2 af[8], bf[8];
#pragma unroll
            for (int mi = 0; mi < 4; mi++)
#pragma unroll
                for (int hi = 0; hi < 2; hi++) {
                    int row = m_w + mi * 16 + hi * 8 + group;
                    int sl = ((tig * 2 + s) ^ ((row >> 1) & 1)) << 1;
                    af[mi * 2 + hi] = *(const uint2*)&ab[row * 16 + sl];
                }
#pragma unroll
            for (int ni = 0; ni < 8; ni++) {
                int row = n_w + ni * 8 + group;
                int sl = ((tig * 2 + s) ^ ((row >> 1) & 1)) << 1;
                bf[ni] = *(const uint2*)&bb2[row * 16 + sl];
            }
#pragma unroll
            for (int mi = 0; mi < 4; mi++)
#pragma unroll
                for (int ni = 0; ni < 8; ni++)
                    mma_f16(acc[mi][ni],
                            af[mi * 2].x, af[mi * 2 + 1].x,
                            af[mi * 2].y, af[mi * 2 + 1].y,
                            bf[ni].x, bf[ni].y);
        }

        if (c < 7) LG_STS(smu + ((c + 1) & 1) * LG_BUF_UINTS);
        __syncthreads();
    }

    // epilogue
#pragma unroll
    for (int mi = 0; mi < 4; mi++) {
        int gm0 = m_blk + m_w + mi * 16 + group;
#pragma unroll
        for (int ni = 0; ni < 8; ni++) {
            int gn = n_blk + n_w + ni * 8 + tig * 2;
            float2 bbv = *(const float2*)(fcb + gn);
            float2 o0, o1;
            o0.x = acc[mi][ni][0] + bbv.x; o0.y = acc[mi][ni][1] + bbv.y;
            o1.x = acc[mi][ni][2] + bbv.x; o1.y = acc[mi][ni][3] + bbv.y;
            *(float2*)(out + (long)gm0 * V_OUT + gn)       = o0;
            *(float2*)(out + (long)(gm0 + 8) * V_OUT + gn) = o1;
        }
    }
#undef LG_LOAD
#undef LG_STS
}

// ---------------- launch ----------------------------------------------------
extern "C" void kernel_launch(void* const* d_in, const int* in_sizes, int n_in,
                              void* d_out, int out_size) {
    const int*   src     = (const int*)  d_in[0];
    const int*   trg     = (const int*)  d_in[1];
    const float* enc_emb = (const float*)d_in[2];
    const float* enc_Wih = (const float*)d_in[3];
    const float* enc_Whh = (const float*)d_in[4];
    const float* enc_bih = (const float*)d_in[5];
    const float* enc_bhh = (const float*)d_in[6];
    const float* dec_emb = (const float*)d_in[7];
    const float* dec_Wih = (const float*)d_in[8];
    const float* dec_Whh = (const float*)d_in[9];
    const float* dec_bih = (const float*)d_in[10];
    const float* dec_bhh = (const float*)d_in[11];
    const float* fc_W    = (const float*)d_in[12];
    const float* fc_b    = (const float*)d_in[13];
    float* out = (float*)d_out;

    static bool attr_done = false;
    if (!attr_done) {
        cudaFuncSetAttribute((const void*)gru_rec,
                             cudaFuncAttributeMaxDynamicSharedMemorySize,
                             GR_SMEM_BYTES);
        cudaFuncSetAttribute((const void*)logits_f16,
                             cudaFuncAttributeMaxDynamicSharedMemorySize,
                             LG_SMEM_BYTES);
        attr_done = true;
    }

    xg_gemm_all<<<dim3(G_SZ / 64, 80), 256>>>(enc_emb, enc_Wih, enc_bih, src,
                                              dec_emb, dec_Wih, dec_bih, trg);
    gru_rec<<<GR_CTAS, 256, GR_SMEM_BYTES>>>(enc_Whh, enc_bhh, dec_Whh, dec_bhh);
    logits_f16<<<dim3(M_DEC / 256, V_OUT / 128), 256, LG_SMEM_BYTES>>>(fc_W, fc_b, out);
}

// round 6
// speedup vs baseline: 1.6589x; 1.0651x over previous
#include <cuda_runtime.h>
#include <cstdint>

#define B_SZ   64
#define H_SZ   256
#define G_SZ   768            // 3*H
#define T_ENC  48
#define T_DEC  32
#define V_OUT  32000
#define M_ENC  (B_SZ * T_ENC) // 3072
#define M_DEC  (B_SZ * T_DEC) // 2048

#define GR_RANKS 8
#define GR_BPC   4
#define GR_CTAS  128

// logits smem: 2 stages x (A 256x64 uints + B 128x64 uints) = 196608 B
#define LGA_UINTS 16384
#define LGB_UINTS 8192
#define LG_STAGE_UINTS (LGA_UINTS + LGB_UINTS)
#define LG_SMEM_BYTES (2 * LG_STAGE_UINTS * 4)

// ---------------- device scratch ----------------
__device__ float g_xg_enc[M_ENC * G_SZ];
__device__ float g_xg_dec[M_DEC * G_SZ];
__device__ __align__(16) unsigned short g_dech_h[M_DEC * H_SZ];   // fp16 dec hidden
__device__ __align__(16) unsigned short g_fcw_h[V_OUT * H_SZ];    // fp16 fc_W

// ---------------- helpers ----------------
__device__ __forceinline__ void fma2(unsigned long long& d,
                                     unsigned long long a, unsigned long long b) {
    asm("fma.rn.f32x2 %0, %1, %2, %0;" : "+l"(d) : "l"(a), "l"(b));
}
__device__ __forceinline__ void unpack2(unsigned long long v, float& lo, float& hi) {
    asm("mov.b64 {%0,%1}, %2;" : "=f"(lo), "=f"(hi) : "l"(v));
}
__device__ __forceinline__ unsigned long long dup2(float w) {
    unsigned long long d;
    asm("mov.b64 %0, {%1,%1};" : "=l"(d) : "f"(w));
    return d;
}
__device__ __forceinline__ unsigned smem_u32(const void* p) {
    unsigned a;
    asm("{ .reg .u64 t; cvta.to.shared.u64 t, %1; cvt.u32.u64 %0, t; }"
        : "=r"(a) : "l"(p));
    return a;
}
__device__ __forceinline__ unsigned short f2h(float x) {
    unsigned short h;
    asm("cvt.rn.f16.f32 %0, %1;" : "=h"(h) : "f"(x));
    return h;
}
__device__ __forceinline__ unsigned pack_h2(float lo, float hi) {
    unsigned r;
    asm("cvt.rn.f16x2.f32 %0, %1, %2;" : "=r"(r) : "f"(hi), "f"(lo));
    return r;
}
__device__ __forceinline__ void mma_f16(float* d,
                                        unsigned a0, unsigned a1, unsigned a2, unsigned a3,
                                        unsigned b0, unsigned b1) {
    asm volatile(
        "mma.sync.aligned.m16n8k16.row.col.f32.f16.f16.f32 "
        "{%0,%1,%2,%3}, {%4,%5,%6,%7}, {%8,%9}, {%0,%1,%2,%3};"
        : "+f"(d[0]), "+f"(d[1]), "+f"(d[2]), "+f"(d[3])
        : "r"(a0), "r"(a1), "r"(a2), "r"(a3), "r"(b0), "r"(b1));
}

// ---------------- kernel 0: fc_W fp32 -> fp16 ----------------
__global__ void __launch_bounds__(256) cvt_w(const float* __restrict__ fcW) {
    long i = ((long)blockIdx.x * 256 + threadIdx.x) * 8;
    float4 v0 = *(const float4*)(fcW + i);
    float4 v1 = *(const float4*)(fcW + i + 4);
    uint4 o;
    o.x = pack_h2(v0.x, v0.y); o.y = pack_h2(v0.z, v0.w);
    o.z = pack_h2(v1.x, v1.y); o.w = pack_h2(v1.z, v1.w);
    *(uint4*)(g_fcw_h + i) = o;
}

// ---------------- kernel 1: xg = emb[tokens] @ Wih^T + bih (fp32) ----------
__global__ void __launch_bounds__(256) xg_gemm_all(
    const float* __restrict__ enc_emb, const float* __restrict__ enc_Wih,
    const float* __restrict__ enc_bih, const int* __restrict__ src,
    const float* __restrict__ dec_emb, const float* __restrict__ dec_Wih,
    const float* __restrict__ dec_bih, const int* __restrict__ trg)
{
    const int by = blockIdx.y;
    const bool enc = (by < 48);
    const float* emb  = enc ? enc_emb : dec_emb;
    const float* W    = enc ? enc_Wih : dec_Wih;
    const float* bias = enc ? enc_bih : dec_bih;
    float* out        = enc ? g_xg_enc : g_xg_dec;
    const int T       = enc ? T_ENC : T_DEC;
    const int m0      = (enc ? by : by - 48) * 64;

    __shared__ __align__(16) float As[32][68];
    __shared__ __align__(16) float Bs[32][68];
    const int tid = threadIdx.x;
    const int n0 = blockIdx.x * 64;
    const int tx = tid & 15, ty = tid >> 4;

    const float* arow[2];
    const float* brow[2];
    int rowi[2], qi[2];
#pragma unroll
    for (int i = 0; i < 2; i++) {
        int fid = tid + i * 256;
        int row = fid >> 3;
        rowi[i] = row;
        qi[i] = fid & 7;
        int gm = m0 + row;
        int tok;
        if (enc) {
            tok = src[gm];
        } else {
            int t = gm % T;
            int b = gm / T;
            tok = (t == 0) ? 1 : trg[b * T + t - 1];
        }
        arow[i] = emb + (long)tok * H_SZ;
        brow[i] = W + (long)(n0 + row) * H_SZ;
    }

    float acc[4][4];
#pragma unroll
    for (int i = 0; i < 4; i++)
#pragma unroll
        for (int j = 0; j < 4; j++) acc[i][j] = 0.f;

    for (int kc = 0; kc < H_SZ; kc += 32) {
        __syncthreads();
#pragma unroll
        for (int i = 0; i < 2; i++) {
            float4 av = *(const float4*)(arow[i] + kc + qi[i] * 4);
            float4 bv = *(const float4*)(brow[i] + kc + qi[i] * 4);
            int kb = qi[i] * 4, r = rowi[i];
            As[kb + 0][r] = av.x; As[kb + 1][r] = av.y;
            As[kb + 2][r] = av.z; As[kb + 3][r] = av.w;
            Bs[kb + 0][r] = bv.x; Bs[kb + 1][r] = bv.y;
            Bs[kb + 2][r] = bv.z; Bs[kb + 3][r] = bv.w;
        }
        __syncthreads();
#pragma unroll
        for (int kk = 0; kk < 32; kk++) {
            float4 a = *(const float4*)&As[kk][ty * 4];
            float4 b = *(const float4*)&Bs[kk][tx * 4];
            float av[4] = {a.x, a.y, a.z, a.w};
            float bv[4] = {b.x, b.y, b.z, b.w};
#pragma unroll
            for (int i = 0; i < 4; i++)
#pragma unroll
                for (int j = 0; j < 4; j++) acc[i][j] += av[i] * bv[j];
        }
    }

    float4 bb = *(const float4*)(bias + n0 + tx * 4);
    float bj[4] = {bb.x, bb.y, bb.z, bb.w};
#pragma unroll
    for (int i = 0; i < 4; i++) {
        int gm = m0 + ty * 4 + i;
        float4 o;
        o.x = acc[i][0] + bj[0]; o.y = acc[i][1] + bj[1];
        o.z = acc[i][2] + bj[2]; o.w = acc[i][3] + bj[3];
        *(float4*)(out + (long)gm * G_SZ + n0 + tx * 4) = o;
    }
}

// ---------------- kernel 2: cluster GRU, weights in registers --------------
__global__ void __launch_bounds__(256)
__cluster_dims__(GR_RANKS, 1, 1)
gru_rec(const float* __restrict__ encWhh, const float* __restrict__ encBhh,
        const float* __restrict__ decWhh, const float* __restrict__ decBhh)
{
    __shared__ __align__(16) float h_s[2 * 1024];   // [buf][k=256][batch=4]
    __shared__ __align__(16) float redm[32 * 97];

    const int tid  = threadIdx.x;
    const int j    = tid & 31;   // channel within CTA
    const int ksl  = tid >> 5;   // k-slice warp
    const int rank = blockIdx.x & (GR_RANKS - 1);
    const int cid  = blockIdx.x >> 3;

    for (int i = tid; i < 2048; i += 256) h_s[i] = 0.f;
    __syncthreads();

    const bool is_red = (tid < 128);
    const int ch_r = tid & 31;
    const int b_r  = tid >> 5;
    const int cg   = rank * 32 + ch_r;
    const int bg   = cid * GR_BPC + b_r;
    const unsigned h_base = smem_u32(h_s);

    int buf = 0;
    for (int ph = 0; ph < 2; ph++) {
        const int T = ph ? T_DEC : T_ENC;
        const float* xg  = ph ? g_xg_dec : g_xg_enc;
        const float* Bhh = ph ? decBhh : encBhh;
        const float* Wp  = ph ? decWhh : encWhh;

        // per-thread weight registers: 3 gates x 32 k
        float wr[32], wz[32], wn[32];
        {
            const long r0 = (long)(0 * H_SZ + rank * 32 + j) * H_SZ + ksl * 32;
            const long r1 = (long)(1 * H_SZ + rank * 32 + j) * H_SZ + ksl * 32;
            const long r2 = (long)(2 * H_SZ + rank * 32 + j) * H_SZ + ksl * 32;
#pragma unroll
            for (int q = 0; q < 8; q++) {
                float4 a = __ldg((const float4*)(Wp + r0 + q * 4));
                wr[q*4+0]=a.x; wr[q*4+1]=a.y; wr[q*4+2]=a.z; wr[q*4+3]=a.w;
                float4 b = __ldg((const float4*)(Wp + r1 + q * 4));
                wz[q*4+0]=b.x; wz[q*4+1]=b.y; wz[q*4+2]=b.z; wz[q*4+3]=b.w;
                float4 c = __ldg((const float4*)(Wp + r2 + q * 4));
                wn[q*4+0]=c.x; wn[q*4+1]=c.y; wn[q*4+2]=c.z; wn[q*4+3]=c.w;
            }
        }
        float br = 0.f, bz = 0.f, bn = 0.f;
        if (is_red) {
            br = __ldg(Bhh + cg);
            bz = __ldg(Bhh + H_SZ + cg);
            bn = __ldg(Bhh + 2 * H_SZ + cg);
        }

        for (int t = 0; t < T; t++) {
            float xr = 0.f, xz = 0.f, xn = 0.f;
            if (is_red) {
                const float* xp = xg + (long)(bg * T + t) * G_SZ + cg;
                xr = __ldg(xp); xz = __ldg(xp + H_SZ); xn = __ldg(xp + 2 * H_SZ);
            }

            unsigned long long a01[3] = {0ull, 0ull, 0ull};
            unsigned long long a23[3] = {0ull, 0ull, 0ull};
            const float* hb = h_s + buf * 1024 + ksl * 128;   // warp-broadcast reads
#pragma unroll
            for (int kk = 0; kk < 32; kk++) {
                ulonglong2 hv = *(const ulonglong2*)(hb + kk * 4);
                unsigned long long wd;
                wd = dup2(wr[kk]); fma2(a01[0], hv.x, wd); fma2(a23[0], hv.y, wd);
                wd = dup2(wz[kk]); fma2(a01[1], hv.x, wd); fma2(a23[1], hv.y, wd);
                wd = dup2(wn[kk]); fma2(a01[2], hv.x, wd); fma2(a23[2], hv.y, wd);
            }
#pragma unroll
            for (int g = 0; g < 3; g++) {
                float p0, p1, p2, p3;
                unpack2(a01[g], p0, p1);
                unpack2(a23[g], p2, p3);
                float* rp = redm + j * 97 + g * 32 + ksl;
                rp[0]  = p0; rp[8]  = p1;
                rp[16] = p2; rp[24] = p3;
            }
            __syncthreads();

            if (is_red) {
                float s[3];
#pragma unroll
                for (int g = 0; g < 3; g++) {
                    const float* rp = redm + ch_r * 97 + g * 32 + b_r * 8;
                    s[g] = ((rp[0] + rp[1]) + (rp[2] + rp[3]))
                         + ((rp[4] + rp[5]) + (rp[6] + rp[7]));
                }
                float hold = h_s[buf * 1024 + cg * 4 + b_r];
                float r = 1.f / (1.f + __expf(-(xr + s[0] + br)));
                float z = 1.f / (1.f + __expf(-(xz + s[1] + bz)));
                float n = tanhf(xn + r * (s[2] + bn));
                float hnew = (1.f - z) * n + z * hold;

                unsigned laddr = h_base + (unsigned)(((buf ^ 1) * 1024 + cg * 4 + b_r) * 4);
#pragma unroll
                for (int rr = 0; rr < GR_RANKS; rr++) {
                    unsigned ra;
                    asm volatile("mapa.shared::cluster.u32 %0, %1, %2;"
                                 : "=r"(ra) : "r"(laddr), "r"(rr));
                    asm volatile("st.shared::cluster.f32 [%0], %1;"
                                 :: "r"(ra), "f"(hnew) : "memory");
                }
                if (ph) g_dech_h[(long)(bg * T_DEC + t) * H_SZ + cg] = f2h(hnew);
            }
            asm volatile("barrier.cluster.arrive.aligned;" ::: "memory");
            asm volatile("barrier.cluster.wait.aligned;" ::: "memory");
            buf ^= 1;
        }
    }
}

// ---------------- kernel 3: logits (fp16 operands, 256x128 tile) -----------
// smem layout per row: 32 uint2 units; unit u = g*4+t holds h2 {t, t+4} of
// k16-group g; swizzle u' = u ^ ((row&7)<<2). Frag loads = LDS.64, 2 wavefronts.
#define LDG_PAIR(q0, q1, srcp) { \
    q0 = *(const uint4*)(srcp); q1 = *(const uint4*)((srcp) + 8); }

#define STS_UNITS(bufp, r_, g_, q0, q1) { \
    unsigned sw_ = ((unsigned)((r_) & 7)) << 2; \
    uint2* rp_ = (uint2*)((bufp) + (r_) * 64); \
    rp_[((g_)*4+0)^sw_] = make_uint2(q0.x, q1.x); \
    rp_[((g_)*4+1)^sw_] = make_uint2(q0.y, q1.y); \
    rp_[((g_)*4+2)^sw_] = make_uint2(q0.z, q1.z); \
    rp_[((g_)*4+3)^sw_] = make_uint2(q0.w, q1.w); }

__device__ __forceinline__ uint2 ldf(const unsigned* buf, int r, int ks, int tig) {
    return ((const uint2*)(buf + r * 64))[(ks * 4 + tig) ^ ((r & 7) << 2)];
}

__global__ void __launch_bounds__(256, 1) logits_f16(
    const float* __restrict__ fcb, float* __restrict__ out)
{
    extern __shared__ __align__(16) unsigned smu[];
    unsigned* A0 = smu;
    unsigned* B0 = smu + LGA_UINTS;
    unsigned* A1 = smu + LG_STAGE_UINTS;
    unsigned* B1 = A1 + LGA_UINTS;

    const int tid = threadIdx.x;
    const int warp = tid >> 5, lane = tid & 31;
    const int group = lane >> 2, tig = lane & 3;
    const int m_blk = blockIdx.x * 256;
    const int n_blk = blockIdx.y * 128;
    const int m_w = (warp >> 1) * 64;
    const int n_w = (warp & 1) * 64;

    // ---- stage 0 load (k 0..127) ----
#pragma unroll
    for (int ci = 0; ci < 8; ci++) {
        int f = ci * 256 + tid, r = f >> 3, g = f & 7;
        const unsigned short* hp = g_dech_h + (long)(m_blk + r) * 256 + g * 16;
        uint4 q0, q1; LDG_PAIR(q0, q1, hp);
        STS_UNITS(A0, r, g, q0, q1);
    }
#pragma unroll
    for (int ci = 0; ci < 4; ci++) {
        int f = ci * 256 + tid, r = f >> 3, g = f & 7;
        const unsigned short* hp = g_fcw_h + (long)(n_blk + r) * 256 + g * 16;
        uint4 q0, q1; LDG_PAIR(q0, q1, hp);
        STS_UNITS(B0, r, g, q0, q1);
    }
    __syncthreads();

    float acc[4][8][4];
#pragma unroll
    for (int i = 0; i < 4; i++)
#pragma unroll
        for (int jn = 0; jn < 8; jn++)
#pragma unroll
            for (int k = 0; k < 4; k++) acc[i][jn][k] = 0.f;

#define MMA_KS(Abuf, Bbuf, ks_) { \
    uint2 af[8], bfr[8]; \
    _Pragma("unroll") \
    for (int mi = 0; mi < 4; mi++) { \
        af[2*mi]   = ldf(Abuf, m_w + mi * 16 + group,     ks_, tig); \
        af[2*mi+1] = ldf(Abuf, m_w + mi * 16 + 8 + group, ks_, tig); \
    } \
    _Pragma("unroll") \
    for (int ni = 0; ni < 8; ni++) \
        bfr[ni] = ldf(Bbuf, n_w + ni * 8 + group, ks_, tig); \
    _Pragma("unroll") \
    for (int mi = 0; mi < 4; mi++) \
        _Pragma("unroll") \
        for (int ni = 0; ni < 8; ni++) \
            mma_f16(acc[mi][ni], af[2*mi].x, af[2*mi+1].x, af[2*mi].y, af[2*mi+1].y, \
                    bfr[ni].x, bfr[ni].y); }

    // ---- stage0 mma interleaved with stage1 load (quarters) ----
#pragma unroll
    for (int qtr = 0; qtr < 4; qtr++) {
        // issue stage-1 LDGs for this quarter
        int fa0 = (qtr * 2 + 0) * 256 + tid, ra0 = fa0 >> 3, ga0 = fa0 & 7;
        int fa1 = (qtr * 2 + 1) * 256 + tid, ra1 = fa1 >> 3, ga1 = fa1 & 7;
        int fb  = qtr * 256 + tid,           rb  = fb >> 3,  gb  = fb & 7;
        const unsigned short* pa0 = g_dech_h + (long)(m_blk + ra0) * 256 + 128 + ga0 * 16;
        const unsigned short* pa1 = g_dech_h + (long)(m_blk + ra1) * 256 + 128 + ga1 * 16;
        const unsigned short* pb  = g_fcw_h  + (long)(n_blk + rb)  * 256 + 128 + gb  * 16;
        uint4 qa00, qa01, qa10, qa11, qb0, qb1;
        LDG_PAIR(qa00, qa01, pa0);
        LDG_PAIR(qa10, qa11, pa1);
        LDG_PAIR(qb0,  qb1,  pb);

        MMA_KS(A0, B0, qtr * 2 + 0);
        MMA_KS(A0, B0, qtr * 2 + 1);

        STS_UNITS(A1, ra0, ga0, qa00, qa01);
        STS_UNITS(A1, ra1, ga1, qa10, qa11);
        STS_UNITS(B1, rb,  gb,  qb0,  qb1);
    }
    __syncthreads();

    // ---- stage1 mma ----
#pragma unroll
    for (int ks = 0; ks < 8; ks++) {
        MMA_KS(A1, B1, ks);
    }

    // ---- epilogue ----
#pragma unroll
    for (int mi = 0; mi < 4; mi++) {
        int gm0 = m_blk + m_w + mi * 16 + group;
#pragma unroll
        for (int ni = 0; ni < 8; ni++) {
            int gn = n_blk + n_w + ni * 8 + tig * 2;
            float2 bbv = *(const float2*)(fcb + gn);
            float2 o0, o1;
            o0.x = acc[mi][ni][0] + bbv.x; o0.y = acc[mi][ni][1] + bbv.y;
            o1.x = acc[mi][ni][2] + bbv.x; o1.y = acc[mi][ni][3] + bbv.y;
            *(float2*)(out + (long)gm0 * V_OUT + gn)       = o0;
            *(float2*)(out + (long)(gm0 + 8) * V_OUT + gn) = o1;
        }
    }
#undef MMA_KS
}

// ---------------- launch ----------------
extern "C" void kernel_launch(void* const* d_in, const int* in_sizes, int n_in,
                              void* d_out, int out_size) {
    const int*   src     = (const int*)  d_in[0];
    const int*   trg     = (const int*)  d_in[1];
    const float* enc_emb = (const float*)d_in[2];
    const float* enc_Wih = (const float*)d_in[3];
    const float* enc_Whh = (const float*)d_in[4];
    const float* enc_bih = (const float*)d_in[5];
    const float* enc_bhh = (const float*)d_in[6];
    const float* dec_emb = (const float*)d_in[7];
    const float* dec_Wih = (const float*)d_in[8];
    const float* dec_Whh = (const float*)d_in[9];
    const float* dec_bih = (const float*)d_in[10];
    const float* dec_bhh = (const float*)d_in[11];
    const float* fc_W    = (const float*)d_in[12];
    const float* fc_b    = (const float*)d_in[13];
    float* out = (float*)d_out;

    static bool attr_done = false;
    if (!attr_done) {
        cudaFuncSetAttribute((const void*)logits_f16,
                             cudaFuncAttributeMaxDynamicSharedMemorySize,
                             LG_SMEM_BYTES);
        attr_done = true;
    }

    cvt_w<<<V_OUT * H_SZ / (256 * 8), 256>>>(fc_W);
    xg_gemm_all<<<dim3(G_SZ / 64, 80), 256>>>(enc_emb, enc_Wih, enc_bih, src,
                                              dec_emb, dec_Wih, dec_bih, trg);
    gru_rec<<<GR_CTAS, 256>>>(enc_Whh, enc_bhh, dec_Whh, dec_bhh);
    logits_f16<<<dim3(M_DEC / 256, V_OUT / 128), 256, LG_SMEM_BYTES>>>(fc_b, out);
}

// round 7
// speedup vs baseline: 2.0639x; 1.2441x over previous
#include <cuda_runtime.h>
#include <cstdint>

#define B_SZ   64
#define H_SZ   256
#define G_SZ   768            // 3*H
#define T_ENC  48
#define T_DEC  32
#define V_OUT  32000
#define M_ENC  (B_SZ * T_ENC) // 3072
#define M_DEC  (B_SZ * T_DEC) // 2048

#define GR_RANKS 8
#define GR_BPC   4
#define GR_CTAS  128

// logits: 128x128 tile, k-chunk 64, 2-stage cp.async, 2 CTA/SM
#define LT_A_BYTES 16384
#define LT_STAGE   32768
#define LT_SMEM    65536

// ---------------- device scratch ----------------
__device__ float g_xg_enc[M_ENC * G_SZ];
__device__ float g_xg_dec[M_DEC * G_SZ];
__device__ __align__(16) unsigned short g_dech_h[M_DEC * H_SZ];   // fp16 dec hidden
__device__ __align__(16) unsigned short g_fcw_h[V_OUT * H_SZ];    // fp16 fc_W

// ---------------- helpers ----------------
__device__ __forceinline__ void fma2(unsigned long long& d,
                                     unsigned long long a, unsigned long long b) {
    asm("fma.rn.f32x2 %0, %1, %2, %0;" : "+l"(d) : "l"(a), "l"(b));
}
__device__ __forceinline__ void unpack2(unsigned long long v, float& lo, float& hi) {
    asm("mov.b64 {%0,%1}, %2;" : "=f"(lo), "=f"(hi) : "l"(v));
}
__device__ __forceinline__ unsigned long long dup2(float w) {
    unsigned long long d;
    asm("mov.b64 %0, {%1,%1};" : "=l"(d) : "f"(w));
    return d;
}
__device__ __forceinline__ unsigned smem_u32(const void* p) {
    unsigned a;
    asm("{ .reg .u64 t; cvta.to.shared.u64 t, %1; cvt.u32.u64 %0, t; }"
        : "=r"(a) : "l"(p));
    return a;
}
__device__ __forceinline__ unsigned short f2h(float x) {
    unsigned short h;
    asm("cvt.rn.f16.f32 %0, %1;" : "=h"(h) : "f"(x));
    return h;
}
__device__ __forceinline__ unsigned pack_h2(float lo, float hi) {
    unsigned r;
    asm("cvt.rn.f16x2.f32 %0, %1, %2;" : "=r"(r) : "f"(hi), "f"(lo));
    return r;
}
__device__ __forceinline__ void mma_f16(float* d,
                                        unsigned a0, unsigned a1, unsigned a2, unsigned a3,
                                        unsigned b0, unsigned b1) {
    asm volatile(
        "mma.sync.aligned.m16n8k16.row.col.f32.f16.f16.f32 "
        "{%0,%1,%2,%3}, {%4,%5,%6,%7}, {%8,%9}, {%0,%1,%2,%3};"
        : "+f"(d[0]), "+f"(d[1]), "+f"(d[2]), "+f"(d[3])
        : "r"(a0), "r"(a1), "r"(a2), "r"(a3), "r"(b0), "r"(b1));
}

#define LDSM_X4(r0, r1, r2, r3, a) \
    asm volatile("ldmatrix.sync.aligned.m8n8.x4.shared.b16 {%0,%1,%2,%3}, [%4];" \
                 : "=r"(r0), "=r"(r1), "=r"(r2), "=r"(r3) : "r"(a))

#define CP_ASYNC16(dst, src) \
    asm volatile("cp.async.cg.shared.global [%0], [%1], 16;" \
                 :: "r"(dst), "l"(src) : "memory")

#define MBAR_INIT(addr, cnt) \
    asm volatile("mbarrier.init.shared.b64 [%0], %1;" :: "r"(addr), "r"(cnt) : "memory")

#define MBAR_EXPECT(addr, bytes) \
    asm volatile("mbarrier.arrive.expect_tx.shared.b64 _, [%0], %1;" \
                 :: "r"(addr), "r"(bytes) : "memory")

#define MBAR_WAIT(addr, parity) do {                                          \
    unsigned _mb = (addr), _ph = (unsigned)(parity);                          \
    asm volatile("{\n\t.reg .pred P;\n\t"                                     \
        "WL_%=:\n\t"                                                          \
        "mbarrier.try_wait.parity.acquire.cta.shared::cta.b64 P, [%0], %1, 0x989680;\n\t" \
        "@P bra.uni WD_%=;\n\t"                                               \
        "bra.uni WL_%=;\n\t"                                                  \
        "WD_%=:\n\t}" :: "r"(_mb), "r"(_ph) : "memory");                      \
} while (0)

// ---------------- kernel 0: fc_W fp32 -> fp16 ----------------
__global__ void __launch_bounds__(256) cvt_w(const float* __restrict__ fcW) {
    long i = ((long)blockIdx.x * 256 + threadIdx.x) * 8;
    float4 v0 = *(const float4*)(fcW + i);
    float4 v1 = *(const float4*)(fcW + i + 4);
    uint4 o;
    o.x = pack_h2(v0.x, v0.y); o.y = pack_h2(v0.z, v0.w);
    o.z = pack_h2(v1.x, v1.y); o.w = pack_h2(v1.z, v1.w);
    *(uint4*)(g_fcw_h + i) = o;
}

// ---------------- kernel 1: xg = emb[tokens] @ Wih^T + bih (fp32) ----------
__global__ void __launch_bounds__(256) xg_gemm_all(
    const float* __restrict__ enc_emb, const float* __restrict__ enc_Wih,
    const float* __restrict__ enc_bih, const int* __restrict__ src,
    const float* __restrict__ dec_emb, const float* __restrict__ dec_Wih,
    const float* __restrict__ dec_bih, const int* __restrict__ trg)
{
    const int by = blockIdx.y;
    const bool enc = (by < 48);
    const float* emb  = enc ? enc_emb : dec_emb;
    const float* W    = enc ? enc_Wih : dec_Wih;
    const float* bias = enc ? enc_bih : dec_bih;
    float* out        = enc ? g_xg_enc : g_xg_dec;
    const int T       = enc ? T_ENC : T_DEC;
    const int m0      = (enc ? by : by - 48) * 64;

    __shared__ __align__(16) float As[32][68];
    __shared__ __align__(16) float Bs[32][68];
    const int tid = threadIdx.x;
    const int n0 = blockIdx.x * 64;
    const int tx = tid & 15, ty = tid >> 4;

    const float* arow[2];
    const float* brow[2];
    int rowi[2], qi[2];
#pragma unroll
    for (int i = 0; i < 2; i++) {
        int fid = tid + i * 256;
        int row = fid >> 3;
        rowi[i] = row;
        qi[i] = fid & 7;
        int gm = m0 + row;
        int tok;
        if (enc) {
            tok = src[gm];
        } else {
            int t = gm % T;
            int b = gm / T;
            tok = (t == 0) ? 1 : trg[b * T + t - 1];
        }
        arow[i] = emb + (long)tok * H_SZ;
        brow[i] = W + (long)(n0 + row) * H_SZ;
    }

    float acc[4][4];
#pragma unroll
    for (int i = 0; i < 4; i++)
#pragma unroll
        for (int j = 0; j < 4; j++) acc[i][j] = 0.f;

    for (int kc = 0; kc < H_SZ; kc += 32) {
        __syncthreads();
#pragma unroll
        for (int i = 0; i < 2; i++) {
            float4 av = *(const float4*)(arow[i] + kc + qi[i] * 4);
            float4 bv = *(const float4*)(brow[i] + kc + qi[i] * 4);
            int kb = qi[i] * 4, r = rowi[i];
            As[kb + 0][r] = av.x; As[kb + 1][r] = av.y;
            As[kb + 2][r] = av.z; As[kb + 3][r] = av.w;
            Bs[kb + 0][r] = bv.x; Bs[kb + 1][r] = bv.y;
            Bs[kb + 2][r] = bv.z; Bs[kb + 3][r] = bv.w;
        }
        __syncthreads();
#pragma unroll
        for (int kk = 0; kk < 32; kk++) {
            float4 a = *(const float4*)&As[kk][ty * 4];
            float4 b = *(const float4*)&Bs[kk][tx * 4];
            float av[4] = {a.x, a.y, a.z, a.w};
            float bv[4] = {b.x, b.y, b.z, b.w};
#pragma unroll
            for (int i = 0; i < 4; i++)
#pragma unroll
                for (int j = 0; j < 4; j++) acc[i][j] += av[i] * bv[j];
        }
    }

    float4 bb = *(const float4*)(bias + n0 + tx * 4);
    float bj[4] = {bb.x, bb.y, bb.z, bb.w};
#pragma unroll
    for (int i = 0; i < 4; i++) {
        int gm = m0 + ty * 4 + i;
        float4 o;
        o.x = acc[i][0] + bj[0]; o.y = acc[i][1] + bj[1];
        o.z = acc[i][2] + bj[2]; o.w = acc[i][3] + bj[3];
        *(float4*)(out + (long)gm * G_SZ + n0 + tx * 4) = o;
    }
}

// ---------------- kernel 2: cluster GRU, st.async h exchange ----------------
__global__ void __launch_bounds__(256)
__cluster_dims__(GR_RANKS, 1, 1)
gru_rec(const float* __restrict__ encWhh, const float* __restrict__ encBhh,
        const float* __restrict__ decWhh, const float* __restrict__ decBhh)
{
    __shared__ __align__(16) float h_s[2 * 1024];   // [buf][k=256][batch=4]
    __shared__ __align__(16) float redm[32 * 97];
    __shared__ __align__(16) unsigned long long h_mb[2];

    const int tid  = threadIdx.x;
    const int j    = tid & 31;
    const int ksl  = tid >> 5;
    const int rank = blockIdx.x & (GR_RANKS - 1);
    const int cid  = blockIdx.x >> 3;

    for (int i = tid; i < 2048; i += 256) h_s[i] = 0.f;
    if (tid == 0) {
        MBAR_INIT(smem_u32(&h_mb[0]), 1);
        MBAR_INIT(smem_u32(&h_mb[1]), 1);
        MBAR_EXPECT(smem_u32(&h_mb[0]), 4096u);
        MBAR_EXPECT(smem_u32(&h_mb[1]), 4096u);
    }
    __syncthreads();
    asm volatile("barrier.cluster.arrive.aligned;" ::: "memory");
    asm volatile("barrier.cluster.wait.aligned;" ::: "memory");

    const bool is_red = (tid < 128);
    const int ch_r = tid & 31;
    const int b_r  = tid >> 5;
    const int cg   = rank * 32 + ch_r;
    const int bg   = cid * GR_BPC + b_r;
    const unsigned h_base = smem_u32(h_s);
    const unsigned mb_base = smem_u32(&h_mb[0]);

    int buf = 0;
    int par0 = 0, par1 = 0;
    bool first = true;
    for (int ph = 0; ph < 2; ph++) {
        const int T = ph ? T_DEC : T_ENC;
        const float* xg  = ph ? g_xg_dec : g_xg_enc;
        const float* Bhh = ph ? decBhh : encBhh;
        const float* Wp  = ph ? decWhh : encWhh;

        float wr[32], wz[32], wn[32];
        {
            const long r0 = (long)(0 * H_SZ + rank * 32 + j) * H_SZ + ksl * 32;
            const long r1 = (long)(1 * H_SZ + rank * 32 + j) * H_SZ + ksl * 32;
            const long r2 = (long)(2 * H_SZ + rank * 32 + j) * H_SZ + ksl * 32;
#pragma unroll
            for (int q = 0; q < 8; q++) {
                float4 a = __ldg((const float4*)(Wp + r0 + q * 4));
                wr[q*4+0]=a.x; wr[q*4+1]=a.y; wr[q*4+2]=a.z; wr[q*4+3]=a.w;
                float4 b = __ldg((const float4*)(Wp + r1 + q * 4));
                wz[q*4+0]=b.x; wz[q*4+1]=b.y; wz[q*4+2]=b.z; wz[q*4+3]=b.w;
                float4 c = __ldg((const float4*)(Wp + r2 + q * 4));
                wn[q*4+0]=c.x; wn[q*4+1]=c.y; wn[q*4+2]=c.z; wn[q*4+3]=c.w;
            }
        }
        float br = 0.f, bz = 0.f, bn = 0.f;
        if (is_red) {
            br = __ldg(Bhh + cg);
            bz = __ldg(Bhh + H_SZ + cg);
            bn = __ldg(Bhh + 2 * H_SZ + cg);
        }

        for (int t = 0; t < T; t++) {
            if (!first) {
                // wait for this buffer's h data (stores from previous step)
                unsigned mb = mb_base + buf * 8;
                int par = buf ? par1 : par0;
                MBAR_WAIT(mb, par);
                if (buf) par1 ^= 1; else par0 ^= 1;
                if (tid == 0) MBAR_EXPECT(mb, 4096u);   // re-arm for next round
            }
            first = false;

            float xr = 0.f, xz = 0.f, xn = 0.f;
            if (is_red) {
                const float* xp = xg + (long)(bg * T + t) * G_SZ + cg;
                xr = __ldg(xp); xz = __ldg(xp + H_SZ); xn = __ldg(xp + 2 * H_SZ);
            }

            unsigned long long a01[3] = {0ull, 0ull, 0ull};
            unsigned long long a23[3] = {0ull, 0ull, 0ull};
            const float* hb = h_s + buf * 1024 + ksl * 128;
#pragma unroll
            for (int kk = 0; kk < 32; kk++) {
                ulonglong2 hv = *(const ulonglong2*)(hb + kk * 4);
                unsigned long long wd;
                wd = dup2(wr[kk]); fma2(a01[0], hv.x, wd); fma2(a23[0], hv.y, wd);
                wd = dup2(wz[kk]); fma2(a01[1], hv.x, wd); fma2(a23[1], hv.y, wd);
                wd = dup2(wn[kk]); fma2(a01[2], hv.x, wd); fma2(a23[2], hv.y, wd);
            }
#pragma unroll
            for (int g = 0; g < 3; g++) {
                float p0, p1, p2, p3;
                unpack2(a01[g], p0, p1);
                unpack2(a23[g], p2, p3);
                float* rp = redm + j * 97 + g * 32 + ksl;
                rp[0]  = p0; rp[8]  = p1;
                rp[16] = p2; rp[24] = p3;
            }
            __syncthreads();

            if (is_red) {
                float s[3];
#pragma unroll
                for (int g = 0; g < 3; g++) {
                    const float* rp = redm + ch_r * 97 + g * 32 + b_r * 8;
                    s[g] = ((rp[0] + rp[1]) + (rp[2] + rp[3]))
                         + ((rp[4] + rp[5]) + (rp[6] + rp[7]));
                }
                float hold = h_s[buf * 1024 + cg * 4 + b_r];
                float r = 1.f / (1.f + __expf(-(xr + s[0] + br)));
                float z = 1.f / (1.f + __expf(-(xz + s[1] + bz)));
                float n = tanhf(xn + r * (s[2] + bn));
                float hnew = (1.f - z) * n + z * hold;

                const int nb = buf ^ 1;
                unsigned laddr = h_base + (unsigned)((nb * 1024 + cg * 4 + b_r) * 4);
                unsigned lmb   = mb_base + nb * 8;
#pragma unroll
                for (int rr = 0; rr < GR_RANKS; rr++) {
                    unsigned ra, rm;
                    asm volatile("mapa.shared::cluster.u32 %0, %1, %2;"
                                 : "=r"(ra) : "r"(laddr), "r"(rr));
                    asm volatile("mapa.shared::cluster.u32 %0, %1, %2;"
                                 : "=r"(rm) : "r"(lmb), "r"(rr));
                    asm volatile(
                        "st.async.shared::cluster.mbarrier::complete_tx::bytes.f32 [%0], %1, [%2];"
                        :: "r"(ra), "f"(hnew), "r"(rm) : "memory");
                }
                if (ph) g_dech_h[(long)(bg * T_DEC + t) * H_SZ + cg] = f2h(hnew);
            }
            buf ^= 1;
        }
    }
    // drain: wait for the final round's stores, then cluster-exit barrier
    {
        unsigned mb = mb_base + buf * 8;
        int par = buf ? par1 : par0;
        MBAR_WAIT(mb, par);
    }
    asm volatile("barrier.cluster.arrive.aligned;" ::: "memory");
    asm volatile("barrier.cluster.wait.aligned;" ::: "memory");
}

// ---------------- kernel 3: logits, cp.async + ldmatrix, 2 CTA/SM ----------
// 128x128 tile, k-chunk 64, 2-stage pipeline. Row = 128B (64 halves) = 8
// 16B units; unit u stored at u ^ (row&7). ldmatrix.x4 frag loads.
__global__ void __launch_bounds__(256, 2) logits_f16(
    const float* __restrict__ fcb, float* __restrict__ out)
{
    extern __shared__ __align__(16) char smc[];
    const unsigned sb = smem_u32(smc);
    const int tid = threadIdx.x;
    const int warp = tid >> 5, lane = tid & 31;
    const int group = lane >> 2, tig = lane & 3;
    const int m_blk = blockIdx.x * 128;
    const int n_blk = blockIdx.y * 128;
    const int m_w = (warp & 3) * 32;
    const int n_w = (warp >> 2) * 64;

    // per-thread cp.async assignments: 4 A units + 4 B units per chunk
    const int cp_row = tid >> 1;                 // 0..127 (two units per row pair)
    const int cp_u0  = (tid & 1) * 4;            // units 0-3 or 4-7... no: use f mapping

#define LT_ISSUE(c_, s_) do {                                                 \
    unsigned ab_ = sb + (s_) * LT_STAGE;                                      \
    unsigned bb_ = ab_ + LT_A_BYTES;                                          \
    _Pragma("unroll")                                                         \
    for (int i_ = 0; i_ < 4; i_++) {                                          \
        int f_ = i_ * 256 + tid;                                              \
        int r_ = f_ >> 3, u_ = f_ & 7;                                        \
        unsigned d_ = ab_ + r_ * 128 + ((u_ ^ (r_ & 7)) << 4);                \
        const void* s2_ = g_dech_h + (long)(m_blk + r_) * 256 + (c_) * 64 + u_ * 8; \
        CP_ASYNC16(d_, s2_);                                                  \
    }                                                                         \
    _Pragma("unroll")                                                         \
    for (int i_ = 0; i_ < 4; i_++) {                                          \
        int f_ = i_ * 256 + tid;                                              \
        int r_ = f_ >> 3, u_ = f_ & 7;                                        \
        unsigned d_ = bb_ + r_ * 128 + ((u_ ^ (r_ & 7)) << 4);                \
        const void* s2_ = g_fcw_h + (long)(n_blk + r_) * 256 + (c_) * 64 + u_ * 8; \
        CP_ASYNC16(d_, s2_);                                                  \
    }                                                                         \
    asm volatile("cp.async.commit_group;" ::: "memory");                      \
} while (0)

    float acc[2][8][4];
#pragma unroll
    for (int i = 0; i < 2; i++)
#pragma unroll
        for (int jn = 0; jn < 8; jn++)
#pragma unroll
            for (int k = 0; k < 4; k++) acc[i][jn][k] = 0.f;

    LT_ISSUE(0, 0);
    LT_ISSUE(1, 1);

    // precomputed lane geometry
    const int a_row0 = m_w + ((lane >> 3) & 1) * 8 + (lane & 7);  // + mi*16
    const int a_usel = lane >> 4;                                  // 0/1
    const int b_row0 = n_w + (lane & 7);                           // + ni*8
    const int b_usel = lane >> 3;                                  // 0..3

#pragma unroll
    for (int c = 0; c < 4; c++) {
        if (c < 3) asm volatile("cp.async.wait_group 1;" ::: "memory");
        else       asm volatile("cp.async.wait_group 0;" ::: "memory");
        __syncthreads();

        unsigned ab = sb + (c & 1) * LT_STAGE;
        unsigned bb = ab + LT_A_BYTES;

        unsigned bf[8][4];
#pragma unroll
        for (int ks = 0; ks < 4; ks++) {
            if ((ks & 1) == 0) {
                const int p = ks >> 1;
#pragma unroll
                for (int ni = 0; ni < 8; ni++) {
                    int row = b_row0 + ni * 8;
                    int u = 4 * p + b_usel;
                    unsigned addr = bb + row * 128 + ((u ^ (row & 7)) << 4);
                    LDSM_X4(bf[ni][0], bf[ni][1], bf[ni][2], bf[ni][3], addr);
                }
            }
            unsigned af[2][4];
#pragma unroll
            for (int mi = 0; mi < 2; mi++) {
                int row = a_row0 + mi * 16;
                int u = 2 * ks + a_usel;
                unsigned addr = ab + row * 128 + ((u ^ (row & 7)) << 4);
                LDSM_X4(af[mi][0], af[mi][1], af[mi][2], af[mi][3], addr);
            }
            const int h = (ks & 1) * 2;
#pragma unroll
            for (int mi = 0; mi < 2; mi++)
#pragma unroll
                for (int ni = 0; ni < 8; ni++)
                    mma_f16(acc[mi][ni], af[mi][0], af[mi][1], af[mi][2], af[mi][3],
                            bf[ni][h], bf[ni][h + 1]);
        }
        __syncthreads();
        if (c < 2) LT_ISSUE(c + 2, c & 1);
    }

    // epilogue
#pragma unroll
    for (int mi = 0; mi < 2; mi++) {
        int gm0 = m_blk + m_w + mi * 16 + group;
#pragma unroll
        for (int ni = 0; ni < 8; ni++) {
            int gn = n_blk + n_w + ni * 8 + tig * 2;
            float2 bbv = *(const float2*)(fcb + gn);
            float2 o0, o1;
            o0.x = acc[mi][ni][0] + bbv.x; o0.y = acc[mi][ni][1] + bbv.y;
            o1.x = acc[mi][ni][2] + bbv.x; o1.y = acc[mi][ni][3] + bbv.y;
            *(float2*)(out + (long)gm0 * V_OUT + gn)       = o0;
            *(float2*)(out + (long)(gm0 + 8) * V_OUT + gn) = o1;
        }
    }
#undef LT_ISSUE
}

// ---------------- launch ----------------
extern "C" void kernel_launch(void* const* d_in, const int* in_sizes, int n_in,
                              void* d_out, int out_size) {
    const int*   src     = (const int*)  d_in[0];
    const int*   trg     = (const int*)  d_in[1];
    const float* enc_emb = (const float*)d_in[2];
    const float* enc_Wih = (const float*)d_in[3];
    const float* enc_Whh = (const float*)d_in[4];
    const float* enc_bih = (const float*)d_in[5];
    const float* enc_bhh = (const float*)d_in[6];
    const float* dec_emb = (const float*)d_in[7];
    const float* dec_Wih = (const float*)d_in[8];
    const float* dec_Whh = (const float*)d_in[9];
    const float* dec_bih = (const float*)d_in[10];
    const float* dec_bhh = (const float*)d_in[11];
    const float* fc_W    = (const float*)d_in[12];
    const float* fc_b    = (const float*)d_in[13];
    float* out = (float*)d_out;

    static bool attr_done = false;
    if (!attr_done) {
        cudaFuncSetAttribute((const void*)logits_f16,
                             cudaFuncAttributeMaxDynamicSharedMemorySize,
                             LT_SMEM);
        attr_done = true;
    }

    cvt_w<<<V_OUT * H_SZ / (256 * 8), 256>>>(fc_W);
    xg_gemm_all<<<dim3(G_SZ / 64, 80), 256>>>(enc_emb, enc_Wih, enc_bih, src,
                                              dec_emb, dec_Wih, dec_bih, trg);
    gru_rec<<<GR_CTAS, 256>>>(enc_Whh, enc_bhh, dec_Whh, dec_bhh);
    logits_f16<<<dim3(M_DEC / 128, V_OUT / 128), 256, LT_SMEM>>>(fc_b, out);
}

// round 8
// speedup vs baseline: 2.6693x; 1.2934x over previous
#include <cuda_runtime.h>
#include <cstdint>

#define B_SZ   64
#define H_SZ   256
#define G_SZ   768            // 3*H
#define T_ENC  48
#define T_DEC  32
#define V_OUT  32000
#define M_ENC  (B_SZ * T_ENC) // 3072
#define M_DEC  (B_SZ * T_DEC) // 2048

// gru: 32 clusters x 4 CTAs, 64 ch per CTA, 2 batches per cluster
#define GR_RANKS 4
#define GR_BPC   2
#define GR_CTAS  128
#define GR_W_FLOATS (3 * 64 * 257)           // smem weights, pad 257
#define GR_SMEM_BYTES (GR_W_FLOATS * 4)      // 197376 (dynamic)

// logits: 128x128 tile, k-chunk 64, 3-stage cp.async, 2 CTA/SM
#define LT_A_BYTES 16384
#define LT_STAGE   32768
#define LT_SMEM    (3 * LT_STAGE)            // 98304

// ---------------- device scratch ----------------
__device__ float g_xg_enc[M_ENC * G_SZ];
__device__ float g_xg_dec[M_DEC * G_SZ];
__device__ __align__(16) unsigned short g_dech_h[M_DEC * H_SZ];   // fp16 dec hidden
__device__ __align__(16) unsigned short g_fcw_h[V_OUT * H_SZ];    // fp16 fc_W

// ---------------- helpers ----------------
__device__ __forceinline__ void fma2(unsigned long long& d,
                                     unsigned long long a, unsigned long long b) {
    asm("fma.rn.f32x2 %0, %1, %2, %0;" : "+l"(d) : "l"(a), "l"(b));
}
__device__ __forceinline__ void unpack2(unsigned long long v, float& lo, float& hi) {
    asm("mov.b64 {%0,%1}, %2;" : "=f"(lo), "=f"(hi) : "l"(v));
}
__device__ __forceinline__ unsigned long long dup2(float w) {
    unsigned long long d;
    asm("mov.b64 %0, {%1,%1};" : "=l"(d) : "f"(w));
    return d;
}
__device__ __forceinline__ unsigned long long pack64(float lo, float hi) {
    unsigned long long d;
    asm("mov.b64 %0, {%1,%2};" : "=l"(d) : "f"(lo), "f"(hi));
    return d;
}
__device__ __forceinline__ unsigned smem_u32(const void* p) {
    unsigned a;
    asm("{ .reg .u64 t; cvta.to.shared.u64 t, %1; cvt.u32.u64 %0, t; }"
        : "=r"(a) : "l"(p));
    return a;
}
__device__ __forceinline__ unsigned short f2h(float x) {
    unsigned short h;
    asm("cvt.rn.f16.f32 %0, %1;" : "=h"(h) : "f"(x));
    return h;
}
__device__ __forceinline__ unsigned pack_h2(float lo, float hi) {
    unsigned r;
    asm("cvt.rn.f16x2.f32 %0, %1, %2;" : "=r"(r) : "f"(hi), "f"(lo));
    return r;
}
__device__ __forceinline__ void mma_f16(float* d,
                                        unsigned a0, unsigned a1, unsigned a2, unsigned a3,
                                        unsigned b0, unsigned b1) {
    asm volatile(
        "mma.sync.aligned.m16n8k16.row.col.f32.f16.f16.f32 "
        "{%0,%1,%2,%3}, {%4,%5,%6,%7}, {%8,%9}, {%0,%1,%2,%3};"
        : "+f"(d[0]), "+f"(d[1]), "+f"(d[2]), "+f"(d[3])
        : "r"(a0), "r"(a1), "r"(a2), "r"(a3), "r"(b0), "r"(b1));
}

#define LDSM_X4(r0, r1, r2, r3, a) \
    asm volatile("ldmatrix.sync.aligned.m8n8.x4.shared.b16 {%0,%1,%2,%3}, [%4];" \
                 : "=r"(r0), "=r"(r1), "=r"(r2), "=r"(r3) : "r"(a))

#define CP_ASYNC16(dst, src) \
    asm volatile("cp.async.cg.shared.global [%0], [%1], 16;" \
                 :: "r"(dst), "l"(src) : "memory")

#define MBAR_INIT(addr, cnt) \
    asm volatile("mbarrier.init.shared.b64 [%0], %1;" :: "r"(addr), "r"(cnt) : "memory")

#define MBAR_EXPECT(addr, bytes) \
    asm volatile("mbarrier.arrive.expect_tx.shared.b64 _, [%0], %1;" \
                 :: "r"(addr), "r"(bytes) : "memory")

#define MBAR_WAIT(addr, parity) do {                                          \
    unsigned _mb = (addr), _ph = (unsigned)(parity);                          \
    asm volatile("{\n\t.reg .pred P;\n\t"                                     \
        "WL_%=:\n\t"                                                          \
        "mbarrier.try_wait.parity.acquire.cta.shared::cta.b64 P, [%0], %1, 0x989680;\n\t" \
        "@P bra.uni WD_%=;\n\t"                                               \
        "bra.uni WL_%=;\n\t"                                                  \
        "WD_%=:\n\t}" :: "r"(_mb), "r"(_ph) : "memory");                      \
} while (0)

// ---------------- kernel 0: fc_W fp32 -> fp16 ----------------
__global__ void __launch_bounds__(256) cvt_w(const float* __restrict__ fcW) {
    long i = ((long)blockIdx.x * 256 + threadIdx.x) * 8;
    float4 v0 = *(const float4*)(fcW + i);
    float4 v1 = *(const float4*)(fcW + i + 4);
    uint4 o;
    o.x = pack_h2(v0.x, v0.y); o.y = pack_h2(v0.z, v0.w);
    o.z = pack_h2(v1.x, v1.y); o.w = pack_h2(v1.z, v1.w);
    *(uint4*)(g_fcw_h + i) = o;
}

// ---------------- kernel 1: xg = emb[tokens] @ Wih^T + bih (fp32) ----------
__global__ void __launch_bounds__(256) xg_gemm_all(
    const float* __restrict__ enc_emb, const float* __restrict__ enc_Wih,
    const float* __restrict__ enc_bih, const int* __restrict__ src,
    const float* __restrict__ dec_emb, const float* __restrict__ dec_Wih,
    const float* __restrict__ dec_bih, const int* __restrict__ trg)
{
    const int by = blockIdx.y;
    const bool enc = (by < 48);
    const float* emb  = enc ? enc_emb : dec_emb;
    const float* W    = enc ? enc_Wih : dec_Wih;
    const float* bias = enc ? enc_bih : dec_bih;
    float* out        = enc ? g_xg_enc : g_xg_dec;
    const int T       = enc ? T_ENC : T_DEC;
    const int m0      = (enc ? by : by - 48) * 64;

    __shared__ __align__(16) float As[32][68];
    __shared__ __align__(16) float Bs[32][68];
    const int tid = threadIdx.x;
    const int n0 = blockIdx.x * 64;
    const int tx = tid & 15, ty = tid >> 4;

    const float* arow[2];
    const float* brow[2];
    int rowi[2], qi[2];
#pragma unroll
    for (int i = 0; i < 2; i++) {
        int fid = tid + i * 256;
        int row = fid >> 3;
        rowi[i] = row;
        qi[i] = fid & 7;
        int gm = m0 + row;
        int tok;
        if (enc) {
            tok = src[gm];
        } else {
            int t = gm % T;
            int b = gm / T;
            tok = (t == 0) ? 1 : trg[b * T + t - 1];
        }
        arow[i] = emb + (long)tok * H_SZ;
        brow[i] = W + (long)(n0 + row) * H_SZ;
    }

    float acc[4][4];
#pragma unroll
    for (int i = 0; i < 4; i++)
#pragma unroll
        for (int j = 0; j < 4; j++) acc[i][j] = 0.f;

    for (int kc = 0; kc < H_SZ; kc += 32) {
        __syncthreads();
#pragma unroll
        for (int i = 0; i < 2; i++) {
            float4 av = *(const float4*)(arow[i] + kc + qi[i] * 4);
            float4 bv = *(const float4*)(brow[i] + kc + qi[i] * 4);
            int kb = qi[i] * 4, r = rowi[i];
            As[kb + 0][r] = av.x; As[kb + 1][r] = av.y;
            As[kb + 2][r] = av.z; As[kb + 3][r] = av.w;
            Bs[kb + 0][r] = bv.x; Bs[kb + 1][r] = bv.y;
            Bs[kb + 2][r] = bv.z; Bs[kb + 3][r] = bv.w;
        }
        __syncthreads();
#pragma unroll
        for (int kk = 0; kk < 32; kk++) {
            float4 a = *(const float4*)&As[kk][ty * 4];
            float4 b = *(const float4*)&Bs[kk][tx * 4];
            float av[4] = {a.x, a.y, a.z, a.w};
            float bv[4] = {b.x, b.y, b.z, b.w};
#pragma unroll
            for (int i = 0; i < 4; i++)
#pragma unroll
                for (int j = 0; j < 4; j++) acc[i][j] += av[i] * bv[j];
        }
    }

    float4 bb = *(const float4*)(bias + n0 + tx * 4);
    float bj[4] = {bb.x, bb.y, bb.z, bb.w};
#pragma unroll
    for (int i = 0; i < 4; i++) {
        int gm = m0 + ty * 4 + i;
        float4 o;
        o.x = acc[i][0] + bj[0]; o.y = acc[i][1] + bj[1];
        o.z = acc[i][2] + bj[2]; o.w = acc[i][3] + bj[3];
        *(float4*)(out + (long)gm * G_SZ + n0 + tx * 4) = o;
    }
}

// ---------------- kernel 2: cluster GRU (4 ranks, packed b64 exchange) -----
// 32 clusters of 4 CTAs; cluster owns 2 batches; CTA rank owns 64 channels.
// Whh slice in smem (reloaded per phase). h replicated per CTA,
// double-buffered [buf][k=256][b=2]. Exchange = 64 reducer threads x
// st.async.b64 x 4 ranks, mbarrier complete_tx (2048 B per buffer).
__global__ void __launch_bounds__(256)
__cluster_dims__(GR_RANKS, 1, 1)
gru_rec(const float* __restrict__ encWhh, const float* __restrict__ encBhh,
        const float* __restrict__ decWhh, const float* __restrict__ decBhh)
{
    extern __shared__ __align__(16) float w_s[];     // [3][64][257]
    __shared__ __align__(16) float h_s[2 * 512];     // [buf][k][b]
    __shared__ __align__(16) float redm[64 * 25];    // [ch][g*8 + b*4 + ksl]
    __shared__ __align__(16) unsigned long long h_mb[2];

    const int tid  = threadIdx.x;
    const int j    = tid & 63;   // channel within CTA
    const int ksl  = tid >> 6;   // k-slice (64 k each)
    const int rank = blockIdx.x & (GR_RANKS - 1);
    const int cid  = blockIdx.x >> 2;

    for (int i = tid; i < 1024; i += 256) h_s[i] = 0.f;
    if (tid == 0) {
        MBAR_INIT(smem_u32(&h_mb[0]), 1);
        MBAR_INIT(smem_u32(&h_mb[1]), 1);
        MBAR_EXPECT(smem_u32(&h_mb[0]), 2048u);
        MBAR_EXPECT(smem_u32(&h_mb[1]), 2048u);
    }
    __syncthreads();
    asm volatile("barrier.cluster.arrive.aligned;" ::: "memory");
    asm volatile("barrier.cluster.wait.aligned;" ::: "memory");

    const bool is_red = (tid < 64);
    const int cg  = rank * 64 + j;          // global channel (for this thread's dot)
    const unsigned h_base = smem_u32(h_s);
    const unsigned mb_base = smem_u32(&h_mb[0]);

    int buf = 0;
    int par0 = 0, par1 = 0;
    bool first = true;
    for (int ph = 0; ph < 2; ph++) {
        const int T = ph ? T_DEC : T_ENC;
        const float* xg  = ph ? g_xg_dec : g_xg_enc;
        const float* Bhh = ph ? decBhh : encBhh;
        const float* Wp  = ph ? decWhh : encWhh;

        // load this phase's Whh slice into smem: rows (g,ch), 256 k, pad 257
        for (int fid = tid; fid < 3 * 64 * 64; fid += 256) {
            int q = fid & 63;       // float4 index
            int r = fid >> 6;       // 0..191 = g*64 + ch
            int g = r >> 6, ch = r & 63;
            float4 v = __ldg((const float4*)(Wp + (long)(g * H_SZ + rank * 64 + ch) * H_SZ + q * 4));
            float* dst = w_s + r * 257 + q * 4;
            dst[0] = v.x; dst[1] = v.y; dst[2] = v.z; dst[3] = v.w;
        }
        float br = 0.f, bz = 0.f, bn = 0.f;
        if (is_red) {
            br = __ldg(Bhh + cg);
            bz = __ldg(Bhh + H_SZ + cg);
            bn = __ldg(Bhh + 2 * H_SZ + cg);
        }
        __syncthreads();

        const float* w0 = w_s + (0 * 64 + j) * 257 + ksl * 64;
        const float* w1 = w_s + (1 * 64 + j) * 257 + ksl * 64;
        const float* w2 = w_s + (2 * 64 + j) * 257 + ksl * 64;

        for (int t = 0; t < T; t++) {
            if (!first) {
                unsigned mb = mb_base + buf * 8;
                int par = buf ? par1 : par0;
                MBAR_WAIT(mb, par);
                if (buf) par1 ^= 1; else par0 ^= 1;
                if (tid == 0) MBAR_EXPECT(mb, 2048u);
            }
            first = false;

            // prefetch xg for both batches (reducers only)
            float xr[2], xz[2], xn[2];
            if (is_red) {
#pragma unroll
                for (int b = 0; b < 2; b++) {
                    const int bg = cid * GR_BPC + b;
                    const float* xp = xg + (long)(bg * T + t) * G_SZ + cg;
                    xr[b] = __ldg(xp); xz[b] = __ldg(xp + H_SZ); xn[b] = __ldg(xp + 2 * H_SZ);
                }
            }

            // partial dots over this thread's 64-k slice (both batches packed)
            unsigned long long a[3] = {0ull, 0ull, 0ull};
            const float* hb = h_s + buf * 512 + ksl * 128;   // [k][2]
#pragma unroll 16
            for (int kk = 0; kk < 64; kk++) {
                unsigned long long hv = *(const unsigned long long*)(hb + kk * 2);
                fma2(a[0], hv, dup2(w0[kk]));
                fma2(a[1], hv, dup2(w1[kk]));
                fma2(a[2], hv, dup2(w2[kk]));
            }
#pragma unroll
            for (int g = 0; g < 3; g++) {
                float p0, p1;
                unpack2(a[g], p0, p1);
                float* rp = redm + j * 25 + g * 8 + ksl;
                rp[0] = p0; rp[4] = p1;
            }
            __syncthreads();

            if (is_red) {
                float hnew[2];
#pragma unroll
                for (int b = 0; b < 2; b++) {
                    float s[3];
#pragma unroll
                    for (int g = 0; g < 3; g++) {
                        const float* rp = redm + j * 25 + g * 8 + b * 4;
                        s[g] = (rp[0] + rp[1]) + (rp[2] + rp[3]);
                    }
                    float hold = h_s[buf * 512 + cg * 2 + b];
                    float r = 1.f / (1.f + __expf(-(xr[b] + s[0] + br)));
                    float z = 1.f / (1.f + __expf(-(xz[b] + s[1] + bz)));
                    float n = tanhf(xn[b] + r * (s[2] + bn));
                    hnew[b] = (1.f - z) * n + z * hold;
                }

                const int nb = buf ^ 1;
                unsigned long long hp = pack64(hnew[0], hnew[1]);
                unsigned laddr = h_base + (unsigned)((nb * 512 + cg * 2) * 4);
                unsigned lmb   = mb_base + nb * 8;
#pragma unroll
                for (int rr = 0; rr < GR_RANKS; rr++) {
                    unsigned ra, rm;
                    asm volatile("mapa.shared::cluster.u32 %0, %1, %2;"
                                 : "=r"(ra) : "r"(laddr), "r"(rr));
                    asm volatile("mapa.shared::cluster.u32 %0, %1, %2;"
                                 : "=r"(rm) : "r"(lmb), "r"(rr));
                    asm volatile(
                        "st.async.shared::cluster.mbarrier::complete_tx::bytes.b64 [%0], %1, [%2];"
                        :: "r"(ra), "l"(hp), "r"(rm) : "memory");
                }
                if (ph) {
#pragma unroll
                    for (int b = 0; b < 2; b++) {
                        const int bg = cid * GR_BPC + b;
                        g_dech_h[(long)(bg * T_DEC + t) * H_SZ + cg] = f2h(hnew[b]);
                    }
                }
            }
            buf ^= 1;
        }
    }
    // drain final round, then exit barrier
    {
        unsigned mb = mb_base + buf * 8;
        int par = buf ? par1 : par0;
        MBAR_WAIT(mb, par);
    }
    asm volatile("barrier.cluster.arrive.aligned;" ::: "memory");
    asm volatile("barrier.cluster.wait.aligned;" ::: "memory");
}

// ---------------- kernel 3: logits, 3-stage cp.async + ldmatrix ------------
__global__ void __launch_bounds__(256, 2) logits_f16(
    const float* __restrict__ fcb, float* __restrict__ out)
{
    extern __shared__ __align__(16) char smc[];
    const unsigned sb = smem_u32(smc);
    const int tid = threadIdx.x;
    const int warp = tid >> 5, lane = tid & 31;
    const int group = lane >> 2, tig = lane & 3;
    const int m_blk = blockIdx.x * 128;
    const int n_blk = blockIdx.y * 128;
    const int m_w = (warp & 3) * 32;
    const int n_w = (warp >> 2) * 64;

#define LT_ISSUE(c_, s_) do {                                                 \
    unsigned ab_ = sb + (s_) * LT_STAGE;                                      \
    unsigned bb_ = ab_ + LT_A_BYTES;                                          \
    _Pragma("unroll")                                                         \
    for (int i_ = 0; i_ < 4; i_++) {                                          \
        int f_ = i_ * 256 + tid;                                              \
        int r_ = f_ >> 3, u_ = f_ & 7;                                        \
        unsigned d_ = ab_ + r_ * 128 + ((u_ ^ (r_ & 7)) << 4);                \
        const void* s2_ = g_dech_h + (long)(m_blk + r_) * 256 + (c_) * 64 + u_ * 8; \
        CP_ASYNC16(d_, s2_);                                                  \
    }                                                                         \
    _Pragma("unroll")                                                         \
    for (int i_ = 0; i_ < 4; i_++) {                                          \
        int f_ = i_ * 256 + tid;                                              \
        int r_ = f_ >> 3, u_ = f_ & 7;                                        \
        unsigned d_ = bb_ + r_ * 128 + ((u_ ^ (r_ & 7)) << 4);                \
        const void* s2_ = g_fcw_h + (long)(n_blk + r_) * 256 + (c_) * 64 + u_ * 8; \
        CP_ASYNC16(d_, s2_);                                                  \
    }                                                                         \
    asm volatile("cp.async.commit_group;" ::: "memory");                      \
} while (0)

    float acc[2][8][4];
#pragma unroll
    for (int i = 0; i < 2; i++)
#pragma unroll
        for (int jn = 0; jn < 8; jn++)
#pragma unroll
            for (int k = 0; k < 4; k++) acc[i][jn][k] = 0.f;

    LT_ISSUE(0, 0);
    LT_ISSUE(1, 1);
    LT_ISSUE(2, 2);

    const int a_row0 = m_w + ((lane >> 3) & 1) * 8 + (lane & 7);
    const int a_usel = lane >> 4;
    const int b_row0 = n_w + (lane & 7);
    const int b_usel = lane >> 3;

#pragma unroll
    for (int c = 0; c < 4; c++) {
        if (c == 0 || c == 1) asm volatile("cp.async.wait_group 2;" ::: "memory");
        else if (c == 2)      asm volatile("cp.async.wait_group 1;" ::: "memory");
        else                  asm volatile("cp.async.wait_group 0;" ::: "memory");
        __syncthreads();

        unsigned ab = sb + (c % 3) * LT_STAGE;
        unsigned bb = ab + LT_A_BYTES;

        unsigned bf[8][4];
#pragma unroll
        for (int ks = 0; ks < 4; ks++) {
            if ((ks & 1) == 0) {
                const int p = ks >> 1;
#pragma unroll
                for (int ni = 0; ni < 8; ni++) {
                    int row = b_row0 + ni * 8;
                    int u = 4 * p + b_usel;
                    unsigned addr = bb + row * 128 + ((u ^ (row & 7)) << 4);
                    LDSM_X4(bf[ni][0], bf[ni][1], bf[ni][2], bf[ni][3], addr);
                }
            }
            unsigned af[2][4];
#pragma unroll
            for (int mi = 0; mi < 2; mi++) {
                int row = a_row0 + mi * 16;
                int u = 2 * ks + a_usel;
                unsigned addr = ab + row * 128 + ((u ^ (row & 7)) << 4);
                LDSM_X4(af[mi][0], af[mi][1], af[mi][2], af[mi][3], addr);
            }
            const int h = (ks & 1) * 2;
#pragma unroll
            for (int mi = 0; mi < 2; mi++)
#pragma unroll
                for (int ni = 0; ni < 8; ni++)
                    mma_f16(acc[mi][ni], af[mi][0], af[mi][1], af[mi][2], af[mi][3],
                            bf[ni][h], bf[ni][h + 1]);
        }
        __syncthreads();
        if (c == 0) LT_ISSUE(3, 0);
    }

    // epilogue
#pragma unroll
    for (int mi = 0; mi < 2; mi++) {
        int gm0 = m_blk + m_w + mi * 16 + group;
#pragma unroll
        for (int ni = 0; ni < 8; ni++) {
            int gn = n_blk + n_w + ni * 8 + tig * 2;
            float2 bbv = *(const float2*)(fcb + gn);
            float2 o0, o1;
            o0.x = acc[mi][ni][0] + bbv.x; o0.y = acc[mi][ni][1] + bbv.y;
            o1.x = acc[mi][ni][2] + bbv.x; o1.y = acc[mi][ni][3] + bbv.y;
            *(float2*)(out + (long)gm0 * V_OUT + gn)       = o0;
            *(float2*)(out + (long)(gm0 + 8) * V_OUT + gn) = o1;
        }
    }
#undef LT_ISSUE
}

// ---------------- launch ----------------
extern "C" void kernel_launch(void* const* d_in, const int* in_sizes, int n_in,
                              void* d_out, int out_size) {
    const int*   src     = (const int*)  d_in[0];
    const int*   trg     = (const int*)  d_in[1];
    const float* enc_emb = (const float*)d_in[2];
    const float* enc_Wih = (const float*)d_in[3];
    const float* enc_Whh = (const float*)d_in[4];
    const float* enc_bih = (const float*)d_in[5];
    const float* enc_bhh = (const float*)d_in[6];
    const float* dec_emb = (const float*)d_in[7];
    const float* dec_Wih = (const float*)d_in[8];
    const float* dec_Whh = (const float*)d_in[9];
    const float* dec_bih = (const float*)d_in[10];
    const float* dec_bhh = (const float*)d_in[11];
    const float* fc_W    = (const float*)d_in[12];
    const float* fc_b    = (const float*)d_in[13];
    float* out = (float*)d_out;

    static bool attr_done = false;
    if (!attr_done) {
        cudaFuncSetAttribute((const void*)gru_rec,
                             cudaFuncAttributeMaxDynamicSharedMemorySize,
                             GR_SMEM_BYTES);
        cudaFuncSetAttribute((const void*)logits_f16,
                             cudaFuncAttributeMaxDynamicSharedMemorySize,
                             LT_SMEM);
        attr_done = true;
    }

    cvt_w<<<V_OUT * H_SZ / (256 * 8), 256>>>(fc_W);
    xg_gemm_all<<<dim3(G_SZ / 64, 80), 256>>>(enc_emb, enc_Wih, enc_bih, src,
                                              dec_emb, dec_Wih, dec_bih, trg);
    gru_rec<<<GR_CTAS, 256, GR_SMEM_BYTES>>>(enc_Whh, enc_bhh, dec_Whh, dec_bhh);
    logits_f16<<<dim3(M_DEC / 128, V_OUT / 128), 256, LT_SMEM>>>(fc_b, out);
}

// round 9
// speedup vs baseline: 2.7911x; 1.0456x over previous
#include <cuda_runtime.h>
#include <cstdint>

#define B_SZ   64
#define H_SZ   256
#define G_SZ   768            // 3*H
#define T_ENC  48
#define T_DEC  32
#define V_OUT  32000
#define M_ENC  (B_SZ * T_ENC) // 3072
#define M_DEC  (B_SZ * T_DEC) // 2048

// gru: 32 clusters x 4 CTAs, 64 ch per CTA, 2 batches per cluster
#define GR_RANKS 4
#define GR_BPC   2
#define GR_CTAS  128
#define GR_W_FLOATS (3 * 64 * 257)
#define GR_SMEM_BYTES (GR_W_FLOATS * 4)

// logits: 128x128 tile, 128 threads (4 warps, 64x64 warp tile),
// k-chunk 64, 3-stage cp.async, 2 CTA/SM
#define LT_A_BYTES 16384
#define LT_STAGE   32768
#define LT_SMEM    (3 * LT_STAGE)            // 98304

// ---------------- device scratch ----------------
__device__ float g_xg_enc[M_ENC * G_SZ];
__device__ float g_xg_dec[M_DEC * G_SZ];
__device__ __align__(16) unsigned short g_dech_h[M_DEC * H_SZ];   // fp16 dec hidden
__device__ __align__(16) unsigned short g_fcw_h[V_OUT * H_SZ];    // fp16 fc_W

// ---------------- helpers ----------------
__device__ __forceinline__ void fma2(unsigned long long& d,
                                     unsigned long long a, unsigned long long b) {
    asm("fma.rn.f32x2 %0, %1, %2, %0;" : "+l"(d) : "l"(a), "l"(b));
}
__device__ __forceinline__ void unpack2(unsigned long long v, float& lo, float& hi) {
    asm("mov.b64 {%0,%1}, %2;" : "=f"(lo), "=f"(hi) : "l"(v));
}
__device__ __forceinline__ unsigned long long dup2(float w) {
    unsigned long long d;
    asm("mov.b64 %0, {%1,%1};" : "=l"(d) : "f"(w));
    return d;
}
__device__ __forceinline__ unsigned long long pack64(float lo, float hi) {
    unsigned long long d;
    asm("mov.b64 %0, {%1,%2};" : "=l"(d) : "f"(lo), "f"(hi));
    return d;
}
__device__ __forceinline__ unsigned smem_u32(const void* p) {
    unsigned a;
    asm("{ .reg .u64 t; cvta.to.shared.u64 t, %1; cvt.u32.u64 %0, t; }"
        : "=r"(a) : "l"(p));
    return a;
}
__device__ __forceinline__ unsigned short f2h(float x) {
    unsigned short h;
    asm("cvt.rn.f16.f32 %0, %1;" : "=h"(h) : "f"(x));
    return h;
}
__device__ __forceinline__ unsigned pack_h2(float lo, float hi) {
    unsigned r;
    asm("cvt.rn.f16x2.f32 %0, %1, %2;" : "=r"(r) : "f"(hi), "f"(lo));
    return r;
}
__device__ __forceinline__ void mma_f16(float* d,
                                        unsigned a0, unsigned a1, unsigned a2, unsigned a3,
                                        unsigned b0, unsigned b1) {
    asm volatile(
        "mma.sync.aligned.m16n8k16.row.col.f32.f16.f16.f32 "
        "{%0,%1,%2,%3}, {%4,%5,%6,%7}, {%8,%9}, {%0,%1,%2,%3};"
        : "+f"(d[0]), "+f"(d[1]), "+f"(d[2]), "+f"(d[3])
        : "r"(a0), "r"(a1), "r"(a2), "r"(a3), "r"(b0), "r"(b1));
}

#define LDSM_X4(r0, r1, r2, r3, a) \
    asm volatile("ldmatrix.sync.aligned.m8n8.x4.shared.b16 {%0,%1,%2,%3}, [%4];" \
                 : "=r"(r0), "=r"(r1), "=r"(r2), "=r"(r3) : "r"(a))

#define CP_ASYNC16(dst, src) \
    asm volatile("cp.async.cg.shared.global [%0], [%1], 16;" \
                 :: "r"(dst), "l"(src) : "memory")

#define MBAR_INIT(addr, cnt) \
    asm volatile("mbarrier.init.shared.b64 [%0], %1;" :: "r"(addr), "r"(cnt) : "memory")

#define MBAR_EXPECT(addr, bytes) \
    asm volatile("mbarrier.arrive.expect_tx.shared.b64 _, [%0], %1;" \
                 :: "r"(addr), "r"(bytes) : "memory")

#define MBAR_WAIT(addr, parity) do {                                          \
    unsigned _mb = (addr), _ph = (unsigned)(parity);                          \
    asm volatile("{\n\t.reg .pred P;\n\t"                                     \
        "WL_%=:\n\t"                                                          \
        "mbarrier.try_wait.parity.acquire.cta.shared::cta.b64 P, [%0], %1, 0x989680;\n\t" \
        "@P bra.uni WD_%=;\n\t"                                               \
        "bra.uni WL_%=;\n\t"                                                  \
        "WD_%=:\n\t}" :: "r"(_mb), "r"(_ph) : "memory");                      \
} while (0)

// ---------------- kernel 0: fc_W fp32 -> fp16 ----------------
__global__ void __launch_bounds__(256) cvt_w(const float* __restrict__ fcW) {
    long i = ((long)blockIdx.x * 256 + threadIdx.x) * 8;
    float4 v0 = *(const float4*)(fcW + i);
    float4 v1 = *(const float4*)(fcW + i + 4);
    uint4 o;
    o.x = pack_h2(v0.x, v0.y); o.y = pack_h2(v0.z, v0.w);
    o.z = pack_h2(v1.x, v1.y); o.w = pack_h2(v1.z, v1.w);
    *(uint4*)(g_fcw_h + i) = o;
}

// ---------------- kernel 1: xg = emb[tokens] @ Wih^T + bih (fp32) ----------
__global__ void __launch_bounds__(256) xg_gemm_all(
    const float* __restrict__ enc_emb, const float* __restrict__ enc_Wih,
    const float* __restrict__ enc_bih, const int* __restrict__ src,
    const float* __restrict__ dec_emb, const float* __restrict__ dec_Wih,
    const float* __restrict__ dec_bih, const int* __restrict__ trg)
{
    const int by = blockIdx.y;
    const bool enc = (by < 48);
    const float* emb  = enc ? enc_emb : dec_emb;
    const float* W    = enc ? enc_Wih : dec_Wih;
    const float* bias = enc ? enc_bih : dec_bih;
    float* out        = enc ? g_xg_enc : g_xg_dec;
    const int T       = enc ? T_ENC : T_DEC;
    const int m0      = (enc ? by : by - 48) * 64;

    __shared__ __align__(16) float As[32][68];
    __shared__ __align__(16) float Bs[32][68];
    const int tid = threadIdx.x;
    const int n0 = blockIdx.x * 64;
    const int tx = tid & 15, ty = tid >> 4;

    const float* arow[2];
    const float* brow[2];
    int rowi[2], qi[2];
#pragma unroll
    for (int i = 0; i < 2; i++) {
        int fid = tid + i * 256;
        int row = fid >> 3;
        rowi[i] = row;
        qi[i] = fid & 7;
        int gm = m0 + row;
        int tok;
        if (enc) {
            tok = src[gm];
        } else {
            int t = gm % T;
            int b = gm / T;
            tok = (t == 0) ? 1 : trg[b * T + t - 1];
        }
        arow[i] = emb + (long)tok * H_SZ;
        brow[i] = W + (long)(n0 + row) * H_SZ;
    }

    float acc[4][4];
#pragma unroll
    for (int i = 0; i < 4; i++)
#pragma unroll
        for (int j = 0; j < 4; j++) acc[i][j] = 0.f;

    for (int kc = 0; kc < H_SZ; kc += 32) {
        __syncthreads();
#pragma unroll
        for (int i = 0; i < 2; i++) {
            float4 av = *(const float4*)(arow[i] + kc + qi[i] * 4);
            float4 bv = *(const float4*)(brow[i] + kc + qi[i] * 4);
            int kb = qi[i] * 4, r = rowi[i];
            As[kb + 0][r] = av.x; As[kb + 1][r] = av.y;
            As[kb + 2][r] = av.z; As[kb + 3][r] = av.w;
            Bs[kb + 0][r] = bv.x; Bs[kb + 1][r] = bv.y;
            Bs[kb + 2][r] = bv.z; Bs[kb + 3][r] = bv.w;
        }
        __syncthreads();
#pragma unroll
        for (int kk = 0; kk < 32; kk++) {
            float4 a = *(const float4*)&As[kk][ty * 4];
            float4 b = *(const float4*)&Bs[kk][tx * 4];
            float av[4] = {a.x, a.y, a.z, a.w};
            float bv[4] = {b.x, b.y, b.z, b.w};
#pragma unroll
            for (int i = 0; i < 4; i++)
#pragma unroll
                for (int j = 0; j < 4; j++) acc[i][j] += av[i] * bv[j];
        }
    }

    float4 bb = *(const float4*)(bias + n0 + tx * 4);
    float bj[4] = {bb.x, bb.y, bb.z, bb.w};
#pragma unroll
    for (int i = 0; i < 4; i++) {
        int gm = m0 + ty * 4 + i;
        float4 o;
        o.x = acc[i][0] + bj[0]; o.y = acc[i][1] + bj[1];
        o.z = acc[i][2] + bj[2]; o.w = acc[i][3] + bj[3];
        *(float4*)(out + (long)gm * G_SZ + n0 + tx * 4) = o;
    }
}

// ---------------- kernel 2: cluster GRU (4 ranks, packed b64 exchange) -----
__global__ void __launch_bounds__(256)
__cluster_dims__(GR_RANKS, 1, 1)
gru_rec(const float* __restrict__ encWhh, const float* __restrict__ encBhh,
        const float* __restrict__ decWhh, const float* __restrict__ decBhh)
{
    extern __shared__ __align__(16) float w_s[];     // [3][64][257]
    __shared__ __align__(16) float h_s[2 * 512];     // [buf][k][b]
    __shared__ __align__(16) float redm[64 * 25];    // [ch][g*8 + b*4 + ksl]
    __shared__ __align__(16) unsigned long long h_mb[2];

    const int tid  = threadIdx.x;
    const int j    = tid & 63;
    const int ksl  = tid >> 6;
    const int rank = blockIdx.x & (GR_RANKS - 1);
    const int cid  = blockIdx.x >> 2;

    for (int i = tid; i < 1024; i += 256) h_s[i] = 0.f;
    if (tid == 0) {
        MBAR_INIT(smem_u32(&h_mb[0]), 1);
        MBAR_INIT(smem_u32(&h_mb[1]), 1);
        MBAR_EXPECT(smem_u32(&h_mb[0]), 2048u);
        MBAR_EXPECT(smem_u32(&h_mb[1]), 2048u);
    }
    __syncthreads();
    asm volatile("barrier.cluster.arrive.aligned;" ::: "memory");
    asm volatile("barrier.cluster.wait.aligned;" ::: "memory");

    const bool is_red = (tid < 64);
    const int cg  = rank * 64 + j;
    const unsigned h_base = smem_u32(h_s);
    const unsigned mb_base = smem_u32(&h_mb[0]);

    int buf = 0;
    int par0 = 0, par1 = 0;
    bool first = true;
    for (int ph = 0; ph < 2; ph++) {
        const int T = ph ? T_DEC : T_ENC;
        const float* xg  = ph ? g_xg_dec : g_xg_enc;
        const float* Bhh = ph ? decBhh : encBhh;
        const float* Wp  = ph ? decWhh : encWhh;

        for (int fid = tid; fid < 3 * 64 * 64; fid += 256) {
            int q = fid & 63;
            int r = fid >> 6;
            int g = r >> 6, ch = r & 63;
            float4 v = __ldg((const float4*)(Wp + (long)(g * H_SZ + rank * 64 + ch) * H_SZ + q * 4));
            float* dst = w_s + r * 257 + q * 4;
            dst[0] = v.x; dst[1] = v.y; dst[2] = v.z; dst[3] = v.w;
        }
        float br = 0.f, bz = 0.f, bn = 0.f;
        if (is_red) {
            br = __ldg(Bhh + cg);
            bz = __ldg(Bhh + H_SZ + cg);
            bn = __ldg(Bhh + 2 * H_SZ + cg);
        }
        __syncthreads();

        const float* w0 = w_s + (0 * 64 + j) * 257 + ksl * 64;
        const float* w1 = w_s + (1 * 64 + j) * 257 + ksl * 64;
        const float* w2 = w_s + (2 * 64 + j) * 257 + ksl * 64;

        for (int t = 0; t < T; t++) {
            if (!first) {
                unsigned mb = mb_base + buf * 8;
                int par = buf ? par1 : par0;
                MBAR_WAIT(mb, par);
                if (buf) par1 ^= 1; else par0 ^= 1;
                if (tid == 0) MBAR_EXPECT(mb, 2048u);
            }
            first = false;

            float xr[2], xz[2], xn[2];
            if (is_red) {
#pragma unroll
                for (int b = 0; b < 2; b++) {
                    const int bg = cid * GR_BPC + b;
                    const float* xp = xg + (long)(bg * T + t) * G_SZ + cg;
                    xr[b] = __ldg(xp); xz[b] = __ldg(xp + H_SZ); xn[b] = __ldg(xp + 2 * H_SZ);
                }
            }

            unsigned long long a[3] = {0ull, 0ull, 0ull};
            const float* hb = h_s + buf * 512 + ksl * 128;
#pragma unroll 16
            for (int kk = 0; kk < 64; kk++) {
                unsigned long long hv = *(const unsigned long long*)(hb + kk * 2);
                fma2(a[0], hv, dup2(w0[kk]));
                fma2(a[1], hv, dup2(w1[kk]));
                fma2(a[2], hv, dup2(w2[kk]));
            }
#pragma unroll
            for (int g = 0; g < 3; g++) {
                float p0, p1;
                unpack2(a[g], p0, p1);
                float* rp = redm + j * 25 + g * 8 + ksl;
                rp[0] = p0; rp[4] = p1;
            }
            __syncthreads();

            if (is_red) {
                float hnew[2];
#pragma unroll
                for (int b = 0; b < 2; b++) {
                    float s[3];
#pragma unroll
                    for (int g = 0; g < 3; g++) {
                        const float* rp = redm + j * 25 + g * 8 + b * 4;
                        s[g] = (rp[0] + rp[1]) + (rp[2] + rp[3]);
                    }
                    float hold = h_s[buf * 512 + cg * 2 + b];
                    float r = 1.f / (1.f + __expf(-(xr[b] + s[0] + br)));
                    float z = 1.f / (1.f + __expf(-(xz[b] + s[1] + bz)));
                    float n = tanhf(xn[b] + r * (s[2] + bn));
                    hnew[b] = (1.f - z) * n + z * hold;
                }

                const int nb = buf ^ 1;
                unsigned long long hp = pack64(hnew[0], hnew[1]);
                unsigned laddr = h_base + (unsigned)((nb * 512 + cg * 2) * 4);
                unsigned lmb   = mb_base + nb * 8;
#pragma unroll
                for (int rr = 0; rr < GR_RANKS; rr++) {
                    unsigned ra, rm;
                    asm volatile("mapa.shared::cluster.u32 %0, %1, %2;"
                                 : "=r"(ra) : "r"(laddr), "r"(rr));
                    asm volatile("mapa.shared::cluster.u32 %0, %1, %2;"
                                 : "=r"(rm) : "r"(lmb), "r"(rr));
                    asm volatile(
                        "st.async.shared::cluster.mbarrier::complete_tx::bytes.b64 [%0], %1, [%2];"
                        :: "r"(ra), "l"(hp), "r"(rm) : "memory");
                }
                if (ph) {
#pragma unroll
                    for (int b = 0; b < 2; b++) {
                        const int bg = cid * GR_BPC + b;
                        g_dech_h[(long)(bg * T_DEC + t) * H_SZ + cg] = f2h(hnew[b]);
                    }
                }
            }
            buf ^= 1;
        }
    }
    {
        unsigned mb = mb_base + buf * 8;
        int par = buf ? par1 : par0;
        MBAR_WAIT(mb, par);
    }
    asm volatile("barrier.cluster.arrive.aligned;" ::: "memory");
    asm volatile("barrier.cluster.wait.aligned;" ::: "memory");
}

// ---------------- kernel 3: logits, 4 warps x 64x64, 3-stage cp.async ------
__global__ void __launch_bounds__(128, 2) logits_f16(
    const float* __restrict__ fcb, float* __restrict__ out)
{
    extern __shared__ __align__(16) char smc[];
    const unsigned sb = smem_u32(smc);
    const int tid = threadIdx.x;
    const int warp = tid >> 5, lane = tid & 31;
    const int group = lane >> 2, tig = lane & 3;
    const int m_blk = blockIdx.x * 128;
    const int n_blk = blockIdx.y * 128;
    const int m_w = (warp >> 1) * 64;
    const int n_w = (warp & 1) * 64;

#define LT_ISSUE(c_, s_) do {                                                 \
    unsigned ab_ = sb + (s_) * LT_STAGE;                                      \
    unsigned bb_ = ab_ + LT_A_BYTES;                                          \
    _Pragma("unroll")                                                         \
    for (int i_ = 0; i_ < 8; i_++) {                                          \
        int f_ = i_ * 128 + tid;                                              \
        int r_ = f_ >> 3, u_ = f_ & 7;                                        \
        unsigned d_ = ab_ + r_ * 128 + ((u_ ^ (r_ & 7)) << 4);                \
        const void* s2_ = g_dech_h + (long)(m_blk + r_) * 256 + (c_) * 64 + u_ * 8; \
        CP_ASYNC16(d_, s2_);                                                  \
    }                                                                         \
    _Pragma("unroll")                                                         \
    for (int i_ = 0; i_ < 8; i_++) {                                          \
        int f_ = i_ * 128 + tid;                                              \
        int r_ = f_ >> 3, u_ = f_ & 7;                                        \
        unsigned d_ = bb_ + r_ * 128 + ((u_ ^ (r_ & 7)) << 4);                \
        const void* s2_ = g_fcw_h + (long)(n_blk + r_) * 256 + (c_) * 64 + u_ * 8; \
        CP_ASYNC16(d_, s2_);                                                  \
    }                                                                         \
    asm volatile("cp.async.commit_group;" ::: "memory");                      \
} while (0)

    float acc[4][8][4];
#pragma unroll
    for (int i = 0; i < 4; i++)
#pragma unroll
        for (int jn = 0; jn < 8; jn++)
#pragma unroll
            for (int k = 0; k < 4; k++) acc[i][jn][k] = 0.f;

    LT_ISSUE(0, 0);
    LT_ISSUE(1, 1);
    LT_ISSUE(2, 2);

    const int a_row0 = m_w + ((lane >> 3) & 1) * 8 + (lane & 7);   // + mi*16
    const int a_usel = lane >> 4;                                   // 0/1
    const int b_row0 = n_w + (lane & 7);                            // + ni*8
    const int b_usel = lane >> 3;                                   // 0..3

#pragma unroll
    for (int c = 0; c < 4; c++) {
        if (c == 0 || c == 1) asm volatile("cp.async.wait_group 2;" ::: "memory");
        else if (c == 2)      asm volatile("cp.async.wait_group 1;" ::: "memory");
        else                  asm volatile("cp.async.wait_group 0;" ::: "memory");
        __syncthreads();

        unsigned ab = sb + (c % 3) * LT_STAGE;
        unsigned bb = ab + LT_A_BYTES;

        unsigned bf[8][4];
#pragma unroll
        for (int ks = 0; ks < 4; ks++) {
            if ((ks & 1) == 0) {
                const int p = ks >> 1;
#pragma unroll
                for (int ni = 0; ni < 8; ni++) {
                    int row = b_row0 + ni * 8;
                    int u = 4 * p + b_usel;
                    unsigned addr = bb + row * 128 + ((u ^ (row & 7)) << 4);
                    LDSM_X4(bf[ni][0], bf[ni][1], bf[ni][2], bf[ni][3], addr);
                }
            }
            unsigned af[4][4];
#pragma unroll
            for (int mi = 0; mi < 4; mi++) {
                int row = a_row0 + mi * 16;
                int u = 2 * ks + a_usel;
                unsigned addr = ab + row * 128 + ((u ^ (row & 7)) << 4);
                LDSM_X4(af[mi][0], af[mi][1], af[mi][2], af[mi][3], addr);
            }
            const int h = (ks & 1) * 2;
#pragma unroll
            for (int mi = 0; mi < 4; mi++)
#pragma unroll
                for (int ni = 0; ni < 8; ni++)
                    mma_f16(acc[mi][ni], af[mi][0], af[mi][1], af[mi][2], af[mi][3],
                            bf[ni][h], bf[ni][h + 1]);
        }
        __syncthreads();
        if (c == 0) LT_ISSUE(3, 0);
    }

    // epilogue
#pragma unroll
    for (int mi = 0; mi < 4; mi++) {
        int gm0 = m_blk + m_w + mi * 16 + group;
#pragma unroll
        for (int ni = 0; ni < 8; ni++) {
            int gn = n_blk + n_w + ni * 8 + tig * 2;
            float2 bbv = *(const float2*)(fcb + gn);
            float2 o0, o1;
            o0.x = acc[mi][ni][0] + bbv.x; o0.y = acc[mi][ni][1] + bbv.y;
            o1.x = acc[mi][ni][2] + bbv.x; o1.y = acc[mi][ni][3] + bbv.y;
            *(float2*)(out + (long)gm0 * V_OUT + gn)       = o0;
            *(float2*)(out + (long)(gm0 + 8) * V_OUT + gn) = o1;
        }
    }
#undef LT_ISSUE
}

// ---------------- launch ----------------
extern "C" void kernel_launch(void* const* d_in, const int* in_sizes, int n_in,
                              void* d_out, int out_size) {
    const int*   src     = (const int*)  d_in[0];
    const int*   trg     = (const int*)  d_in[1];
    const float* enc_emb = (const float*)d_in[2];
    const float* enc_Wih = (const float*)d_in[3];
    const float* enc_Whh = (const float*)d_in[4];
    const float* enc_bih = (const float*)d_in[5];
    const float* enc_bhh = (const float*)d_in[6];
    const float* dec_emb = (const float*)d_in[7];
    const float* dec_Wih = (const float*)d_in[8];
    const float* dec_Whh = (const float*)d_in[9];
    const float* dec_bih = (const float*)d_in[10];
    const float* dec_bhh = (const float*)d_in[11];
    const float* fc_W    = (const float*)d_in[12];
    const float* fc_b    = (const float*)d_in[13];
    float* out = (float*)d_out;

    static bool attr_done = false;
    if (!attr_done) {
        cudaFuncSetAttribute((const void*)gru_rec,
                             cudaFuncAttributeMaxDynamicSharedMemorySize,
                             GR_SMEM_BYTES);
        cudaFuncSetAttribute((const void*)logits_f16,
                             cudaFuncAttributeMaxDynamicSharedMemorySize,
                             LT_SMEM);
        attr_done = true;
    }

    cvt_w<<<V_OUT * H_SZ / (256 * 8), 256>>>(fc_W);
    xg_gemm_all<<<dim3(G_SZ / 64, 80), 256>>>(enc_emb, enc_Wih, enc_bih, src,
                                              dec_emb, dec_Wih, dec_bih, trg);
    gru_rec<<<GR_CTAS, 256, GR_SMEM_BYTES>>>(enc_Whh, enc_bhh, dec_Whh, dec_bhh);
    logits_f16<<<dim3(M_DEC / 128, V_OUT / 128), 128, LT_SMEM>>>(fc_b, out);
}

// round 10
// speedup vs baseline: 2.9844x; 1.0693x over previous
#include <cuda_runtime.h>
#include <cstdint>

#define B_SZ   64
#define H_SZ   256
#define G_SZ   768            // 3*H
#define T_ENC  48
#define T_DEC  32
#define V_OUT  32000
#define M_ENC  (B_SZ * T_ENC) // 3072
#define M_DEC  (B_SZ * T_DEC) // 2048

// gru: 32 clusters x 4 CTAs, 64 ch per CTA, 2 batches per cluster
#define GR_RANKS 4
#define GR_BPC   2
#define GR_CTAS  128
#define GR_WN_FLOATS (64 * 257)              // n-gate weights in smem
#define GR_SMEM_BYTES (GR_WN_FLOATS * 4)     // 65792 (dynamic)

// logits: 128x128 tile, 128 threads (4 warps, 64x64 warp tile),
// k-chunk 64, 3-stage cp.async, 2 CTA/SM
#define LT_A_BYTES 16384
#define LT_STAGE   32768
#define LT_SMEM    (3 * LT_STAGE)            // 98304

// ---------------- device scratch ----------------
__device__ float g_xg_enc[M_ENC * G_SZ];
__device__ float g_xg_dec[M_DEC * G_SZ];
__device__ __align__(16) unsigned short g_dech_h[M_DEC * H_SZ];   // fp16 dec hidden
__device__ __align__(16) unsigned short g_fcw_h[V_OUT * H_SZ];    // fp16 fc_W

// ---------------- helpers ----------------
__device__ __forceinline__ unsigned long long pack64(float lo, float hi) {
    unsigned long long d;
    asm("mov.b64 %0, {%1,%2};" : "=l"(d) : "f"(lo), "f"(hi));
    return d;
}
__device__ __forceinline__ unsigned smem_u32(const void* p) {
    unsigned a;
    asm("{ .reg .u64 t; cvta.to.shared.u64 t, %1; cvt.u32.u64 %0, t; }"
        : "=r"(a) : "l"(p));
    return a;
}
__device__ __forceinline__ unsigned short f2h(float x) {
    unsigned short h;
    asm("cvt.rn.f16.f32 %0, %1;" : "=h"(h) : "f"(x));
    return h;
}
__device__ __forceinline__ unsigned pack_h2(float lo, float hi) {
    unsigned r;
    asm("cvt.rn.f16x2.f32 %0, %1, %2;" : "=r"(r) : "f"(hi), "f"(lo));
    return r;
}
__device__ __forceinline__ void mma_f16(float* d,
                                        unsigned a0, unsigned a1, unsigned a2, unsigned a3,
                                        unsigned b0, unsigned b1) {
    asm volatile(
        "mma.sync.aligned.m16n8k16.row.col.f32.f16.f16.f32 "
        "{%0,%1,%2,%3}, {%4,%5,%6,%7}, {%8,%9}, {%0,%1,%2,%3};"
        : "+f"(d[0]), "+f"(d[1]), "+f"(d[2]), "+f"(d[3])
        : "r"(a0), "r"(a1), "r"(a2), "r"(a3), "r"(b0), "r"(b1));
}

#define LDSM_X4(r0, r1, r2, r3, a) \
    asm volatile("ldmatrix.sync.aligned.m8n8.x4.shared.b16 {%0,%1,%2,%3}, [%4];" \
                 : "=r"(r0), "=r"(r1), "=r"(r2), "=r"(r3) : "r"(a))

#define CP_ASYNC16(dst, src) \
    asm volatile("cp.async.cg.shared.global [%0], [%1], 16;" \
                 :: "r"(dst), "l"(src) : "memory")

#define MBAR_INIT(addr, cnt) \
    asm volatile("mbarrier.init.shared.b64 [%0], %1;" :: "r"(addr), "r"(cnt) : "memory")

#define MBAR_EXPECT(addr, bytes) \
    asm volatile("mbarrier.arrive.expect_tx.shared.b64 _, [%0], %1;" \
                 :: "r"(addr), "r"(bytes) : "memory")

#define MBAR_WAIT(addr, parity) do {                                          \
    unsigned _mb = (addr), _ph = (unsigned)(parity);                          \
    asm volatile("{\n\t.reg .pred P;\n\t"                                     \
        "WL_%=:\n\t"                                                          \
        "mbarrier.try_wait.parity.acquire.cta.shared::cta.b64 P, [%0], %1, 0x989680;\n\t" \
        "@P bra.uni WD_%=;\n\t"                                               \
        "bra.uni WL_%=;\n\t"                                                  \
        "WD_%=:\n\t}" :: "r"(_mb), "r"(_ph) : "memory");                      \
} while (0)

// ---------------- kernel 0: fc_W fp32 -> fp16 ----------------
__global__ void __launch_bounds__(256) cvt_w(const float* __restrict__ fcW) {
    long i = ((long)blockIdx.x * 256 + threadIdx.x) * 8;
    float4 v0 = *(const float4*)(fcW + i);
    float4 v1 = *(const float4*)(fcW + i + 4);
    uint4 o;
    o.x = pack_h2(v0.x, v0.y); o.y = pack_h2(v0.z, v0.w);
    o.z = pack_h2(v1.x, v1.y); o.w = pack_h2(v1.z, v1.w);
    *(uint4*)(g_fcw_h + i) = o;
}

// ---------------- kernel 1: xg = emb[tokens] @ Wih^T + bih (fp32) ----------
__global__ void __launch_bounds__(256) xg_gemm_all(
    const float* __restrict__ enc_emb, const float* __restrict__ enc_Wih,
    const float* __restrict__ enc_bih, const int* __restrict__ src,
    const float* __restrict__ dec_emb, const float* __restrict__ dec_Wih,
    const float* __restrict__ dec_bih, const int* __restrict__ trg)
{
    const int by = blockIdx.y;
    const bool enc = (by < 48);
    const float* emb  = enc ? enc_emb : dec_emb;
    const float* W    = enc ? enc_Wih : dec_Wih;
    const float* bias = enc ? enc_bih : dec_bih;
    float* out        = enc ? g_xg_enc : g_xg_dec;
    const int T       = enc ? T_ENC : T_DEC;
    const int m0      = (enc ? by : by - 48) * 64;

    __shared__ __align__(16) float As[32][68];
    __shared__ __align__(16) float Bs[32][68];
    const int tid = threadIdx.x;
    const int n0 = blockIdx.x * 64;
    const int tx = tid & 15, ty = tid >> 4;

    const float* arow[2];
    const float* brow[2];
    int rowi[2], qi[2];
#pragma unroll
    for (int i = 0; i < 2; i++) {
        int fid = tid + i * 256;
        int row = fid >> 3;
        rowi[i] = row;
        qi[i] = fid & 7;
        int gm = m0 + row;
        int tok;
        if (enc) {
            tok = src[gm];
        } else {
            int t = gm % T;
            int b = gm / T;
            tok = (t == 0) ? 1 : trg[b * T + t - 1];
        }
        arow[i] = emb + (long)tok * H_SZ;
        brow[i] = W + (long)(n0 + row) * H_SZ;
    }

    float acc[4][4];
#pragma unroll
    for (int i = 0; i < 4; i++)
#pragma unroll
        for (int j = 0; j < 4; j++) acc[i][j] = 0.f;

    for (int kc = 0; kc < H_SZ; kc += 32) {
        __syncthreads();
#pragma unroll
        for (int i = 0; i < 2; i++) {
            float4 av = *(const float4*)(arow[i] + kc + qi[i] * 4);
            float4 bv = *(const float4*)(brow[i] + kc + qi[i] * 4);
            int kb = qi[i] * 4, r = rowi[i];
            As[kb + 0][r] = av.x; As[kb + 1][r] = av.y;
            As[kb + 2][r] = av.z; As[kb + 3][r] = av.w;
            Bs[kb + 0][r] = bv.x; Bs[kb + 1][r] = bv.y;
            Bs[kb + 2][r] = bv.z; Bs[kb + 3][r] = bv.w;
        }
        __syncthreads();
#pragma unroll
        for (int kk = 0; kk < 32; kk++) {
            float4 a = *(const float4*)&As[kk][ty * 4];
            float4 b = *(const float4*)&Bs[kk][tx * 4];
            float av[4] = {a.x, a.y, a.z, a.w};
            float bv[4] = {b.x, b.y, b.z, b.w};
#pragma unroll
            for (int i = 0; i < 4; i++)
#pragma unroll
                for (int j = 0; j < 4; j++) acc[i][j] += av[i] * bv[j];
        }
    }

    float4 bb = *(const float4*)(bias + n0 + tx * 4);
    float bj[4] = {bb.x, bb.y, bb.z, bb.w};
#pragma unroll
    for (int i = 0; i < 4; i++) {
        int gm = m0 + ty * 4 + i;
        float4 o;
        o.x = acc[i][0] + bj[0]; o.y = acc[i][1] + bj[1];
        o.z = acc[i][2] + bj[2]; o.w = acc[i][3] + bj[3];
        *(float4*)(out + (long)gm * G_SZ + n0 + tx * 4) = o;
    }
}

// ---------------- kernel 2: cluster GRU v5 ---------------------------------
// 32 clusters x 4 CTAs; cluster owns 2 batches; CTA rank owns 64 channels.
// r,z gate weights REGISTER-resident (64 floats each per thread, reloaded per
// phase); n gate weights in smem [64][257] (conflict-free). Scalar-FFMA dot
// with per-batch accumulators. h layout [buf][k][b] float2 (broadcast LDS.64).
// Exchange: 64 reducers x st.async.b64 x 4 ranks, mbarrier complete_tx.
__global__ void __launch_bounds__(256)
__cluster_dims__(GR_RANKS, 1, 1)
gru_rec(const float* __restrict__ encWhh, const float* __restrict__ encBhh,
        const float* __restrict__ decWhh, const float* __restrict__ decBhh)
{
    extern __shared__ __align__(16) float wn_s[];    // [64][257]
    __shared__ __align__(16) float h_s[2 * 512];     // [buf][k][b]
    __shared__ __align__(16) float redm[64 * 25];    // [ch][g*8 + b*4 + ksl]
    __shared__ __align__(16) unsigned long long h_mb[2];

    const int tid  = threadIdx.x;
    const int j    = tid & 63;   // channel within CTA
    const int ksl  = tid >> 6;   // k-slice (64 k each)
    const int rank = blockIdx.x & (GR_RANKS - 1);
    const int cid  = blockIdx.x >> 2;

    for (int i = tid; i < 1024; i += 256) h_s[i] = 0.f;
    if (tid == 0) {
        MBAR_INIT(smem_u32(&h_mb[0]), 1);
        MBAR_INIT(smem_u32(&h_mb[1]), 1);
        MBAR_EXPECT(smem_u32(&h_mb[0]), 2048u);
        MBAR_EXPECT(smem_u32(&h_mb[1]), 2048u);
    }
    __syncthreads();
    asm volatile("barrier.cluster.arrive.aligned;" ::: "memory");
    asm volatile("barrier.cluster.wait.aligned;" ::: "memory");

    const bool is_red = (tid < 64);
    const int cg  = rank * 64 + j;
    const unsigned h_base = smem_u32(h_s);
    const unsigned mb_base = smem_u32(&h_mb[0]);

    int buf = 0;
    int par0 = 0, par1 = 0;
    bool first = true;
    for (int ph = 0; ph < 2; ph++) {
        const int T = ph ? T_DEC : T_ENC;
        const float* xg  = ph ? g_xg_dec : g_xg_enc;
        const float* Bhh = ph ? decBhh : encBhh;
        const float* Wp  = ph ? decWhh : encWhh;

        // r,z weights into registers: this thread's (ch=j, k-slice=ksl*64..+64)
        float wr[64], wz[64];
        {
            const float* pr = Wp + (long)(0 * H_SZ + rank * 64 + j) * H_SZ + ksl * 64;
            const float* pz = Wp + (long)(1 * H_SZ + rank * 64 + j) * H_SZ + ksl * 64;
#pragma unroll
            for (int q = 0; q < 16; q++) {
                float4 a = __ldg((const float4*)(pr + q * 4));
                wr[q*4+0]=a.x; wr[q*4+1]=a.y; wr[q*4+2]=a.z; wr[q*4+3]=a.w;
                float4 b = __ldg((const float4*)(pz + q * 4));
                wz[q*4+0]=b.x; wz[q*4+1]=b.y; wz[q*4+2]=b.z; wz[q*4+3]=b.w;
            }
        }
        // n weights into smem [ch][257]
        for (int fid = tid; fid < 64 * 64; fid += 256) {
            int q = fid & 63;       // float4 index along k
            int ch = fid >> 6;
            float4 v = __ldg((const float4*)(Wp + (long)(2 * H_SZ + rank * 64 + ch) * H_SZ + q * 4));
            float* dst = wn_s + ch * 257 + q * 4;
            dst[0] = v.x; dst[1] = v.y; dst[2] = v.z; dst[3] = v.w;
        }
        float br = 0.f, bz = 0.f, bn = 0.f;
        if (is_red) {
            br = __ldg(Bhh + cg);
            bz = __ldg(Bhh + H_SZ + cg);
            bn = __ldg(Bhh + 2 * H_SZ + cg);
        }
        __syncthreads();

        const float* wn = wn_s + j * 257 + ksl * 64;

        for (int t = 0; t < T; t++) {
            if (!first) {
                unsigned mb = mb_base + buf * 8;
                int par = buf ? par1 : par0;
                MBAR_WAIT(mb, par);
                if (buf) par1 ^= 1; else par0 ^= 1;
                if (tid == 0) MBAR_EXPECT(mb, 2048u);
            }
            first = false;

            float xr[2], xz[2], xn[2];
            if (is_red) {
#pragma unroll
                for (int b = 0; b < 2; b++) {
                    const int bg = cid * GR_BPC + b;
                    const float* xp = xg + (long)(bg * T + t) * G_SZ + cg;
                    xr[b] = __ldg(xp); xz[b] = __ldg(xp + H_SZ); xn[b] = __ldg(xp + 2 * H_SZ);
                }
            }

            // scalar-FFMA dot over this thread's 64-k slice, both batches
            float ar0 = 0.f, ar1 = 0.f, az0 = 0.f, az1 = 0.f, an0 = 0.f, an1 = 0.f;
            const float* hb = h_s + buf * 512 + ksl * 128;   // [k][2], broadcast
#pragma unroll
            for (int kk = 0; kk < 64; kk++) {
                float2 hv = *(const float2*)(hb + kk * 2);
                float wnv = wn[kk];
                ar0 += hv.x * wr[kk]; ar1 += hv.y * wr[kk];
                az0 += hv.x * wz[kk]; az1 += hv.y * wz[kk];
                an0 += hv.x * wnv;    an1 += hv.y * wnv;
            }
            {
                float* rp = redm + j * 25;
                rp[0 * 8 + 0 + ksl] = ar0; rp[0 * 8 + 4 + ksl] = ar1;
                rp[1 * 8 + 0 + ksl] = az0; rp[1 * 8 + 4 + ksl] = az1;
                rp[2 * 8 + 0 + ksl] = an0; rp[2 * 8 + 4 + ksl] = an1;
            }
            __syncthreads();

            if (is_red) {
                float hnew[2];
#pragma unroll
                for (int b = 0; b < 2; b++) {
                    float s[3];
#pragma unroll
                    for (int g = 0; g < 3; g++) {
                        const float* rp = redm + j * 25 + g * 8 + b * 4;
                        s[g] = (rp[0] + rp[1]) + (rp[2] + rp[3]);
                    }
                    float hold = h_s[buf * 512 + cg * 2 + b];
                    float r = 1.f / (1.f + __expf(-(xr[b] + s[0] + br)));
                    float z = 1.f / (1.f + __expf(-(xz[b] + s[1] + bz)));
                    float n = tanhf(xn[b] + r * (s[2] + bn));
                    hnew[b] = (1.f - z) * n + z * hold;
                }

                const int nb = buf ^ 1;
                unsigned long long hp = pack64(hnew[0], hnew[1]);
                unsigned laddr = h_base + (unsigned)((nb * 512 + cg * 2) * 4);
                unsigned lmb   = mb_base + nb * 8;
#pragma unroll
                for (int rr = 0; rr < GR_RANKS; rr++) {
                    unsigned ra, rm;
                    asm volatile("mapa.shared::cluster.u32 %0, %1, %2;"
                                 : "=r"(ra) : "r"(laddr), "r"(rr));
                    asm volatile("mapa.shared::cluster.u32 %0, %1, %2;"
                                 : "=r"(rm) : "r"(lmb), "r"(rr));
                    asm volatile(
                        "st.async.shared::cluster.mbarrier::complete_tx::bytes.b64 [%0], %1, [%2];"
                        :: "r"(ra), "l"(hp), "r"(rm) : "memory");
                }
                if (ph) {
#pragma unroll
                    for (int b = 0; b < 2; b++) {
                        const int bg = cid * GR_BPC + b;
                        g_dech_h[(long)(bg * T_DEC + t) * H_SZ + cg] = f2h(hnew[b]);
                    }
                }
            }
            buf ^= 1;
        }
        __syncthreads();   // all threads past redm reads before next phase reloads
    }
    {
        unsigned mb = mb_base + buf * 8;
        int par = buf ? par1 : par0;
        MBAR_WAIT(mb, par);
    }
    asm volatile("barrier.cluster.arrive.aligned;" ::: "memory");
    asm volatile("barrier.cluster.wait.aligned;" ::: "memory");
}

// ---------------- kernel 3: logits, 4 warps x 64x64, 3-stage cp.async ------
__global__ void __launch_bounds__(128, 2) logits_f16(
    const float* __restrict__ fcb, float* __restrict__ out)
{
    extern __shared__ __align__(16) char smc[];
    const unsigned sb = smem_u32(smc);
    const int tid = threadIdx.x;
    const int warp = tid >> 5, lane = tid & 31;
    const int group = lane >> 2, tig = lane & 3;
    const int m_blk = blockIdx.x * 128;
    const int n_blk = blockIdx.y * 128;
    const int m_w = (warp >> 1) * 64;
    const int n_w = (warp & 1) * 64;

#define LT_ISSUE(c_, s_) do {                                                 \
    unsigned ab_ = sb + (s_) * LT_STAGE;                                      \
    unsigned bb_ = ab_ + LT_A_BYTES;                                          \
    _Pragma("unroll")                                                         \
    for (int i_ = 0; i_ < 8; i_++) {                                          \
        int f_ = i_ * 128 + tid;                                              \
        int r_ = f_ >> 3, u_ = f_ & 7;                                        \
        unsigned d_ = ab_ + r_ * 128 + ((u_ ^ (r_ & 7)) << 4);                \
        const void* s2_ = g_dech_h + (long)(m_blk + r_) * 256 + (c_) * 64 + u_ * 8; \
        CP_ASYNC16(d_, s2_);                                                  \
    }                                                                         \
    _Pragma("unroll")                                                         \
    for (int i_ = 0; i_ < 8; i_++) {                                          \
        int f_ = i_ * 128 + tid;                                              \
        int r_ = f_ >> 3, u_ = f_ & 7;                                        \
        unsigned d_ = bb_ + r_ * 128 + ((u_ ^ (r_ & 7)) << 4);                \
        const void* s2_ = g_fcw_h + (long)(n_blk + r_) * 256 + (c_) * 64 + u_ * 8; \
        CP_ASYNC16(d_, s2_);                                                  \
    }                                                                         \
    asm volatile("cp.async.commit_group;" ::: "memory");                      \
} while (0)

    float acc[4][8][4];
#pragma unroll
    for (int i = 0; i < 4; i++)
#pragma unroll
        for (int jn = 0; jn < 8; jn++)
#pragma unroll
            for (int k = 0; k < 4; k++) acc[i][jn][k] = 0.f;

    LT_ISSUE(0, 0);
    LT_ISSUE(1, 1);
    LT_ISSUE(2, 2);

    const int a_row0 = m_w + ((lane >> 3) & 1) * 8 + (lane & 7);   // + mi*16
    const int a_usel = lane >> 4;                                   // 0/1
    const int b_row0 = n_w + (lane & 7);                            // + ni*8
    const int b_usel = lane >> 3;                                   // 0..3

#pragma unroll
    for (int c = 0; c < 4; c++) {
        if (c == 0 || c == 1) asm volatile("cp.async.wait_group 2;" ::: "memory");
        else if (c == 2)      asm volatile("cp.async.wait_group 1;" ::: "memory");
        else                  asm volatile("cp.async.wait_group 0;" ::: "memory");
        __syncthreads();

        unsigned ab = sb + (c % 3) * LT_STAGE;
        unsigned bb = ab + LT_A_BYTES;

        unsigned bf[8][4];
#pragma unroll
        for (int ks = 0; ks < 4; ks++) {
            if ((ks & 1) == 0) {
                const int p = ks >> 1;
#pragma unroll
                for (int ni = 0; ni < 8; ni++) {
                    int row = b_row0 + ni * 8;
                    int u = 4 * p + b_usel;
                    unsigned addr = bb + row * 128 + ((u ^ (row & 7)) << 4);
                    LDSM_X4(bf[ni][0], bf[ni][1], bf[ni][2], bf[ni][3], addr);
                }
            }
            unsigned af[4][4];
#pragma unroll
            for (int mi = 0; mi < 4; mi++) {
                int row = a_row0 + mi * 16;
                int u = 2 * ks + a_usel;
                unsigned addr = ab + row * 128 + ((u ^ (row & 7)) << 4);
                LDSM_X4(af[mi][0], af[mi][1], af[mi][2], af[mi][3], addr);
            }
            const int h = (ks & 1) * 2;
#pragma unroll
            for (int mi = 0; mi < 4; mi++)
#pragma unroll
                for (int ni = 0; ni < 8; ni++)
                    mma_f16(acc[mi][ni], af[mi][0], af[mi][1], af[mi][2], af[mi][3],
                            bf[ni][h], bf[ni][h + 1]);
        }
        __syncthreads();
        if (c == 0) LT_ISSUE(3, 0);
    }

    // epilogue
#pragma unroll
    for (int mi = 0; mi < 4; mi++) {
        int gm0 = m_blk + m_w + mi * 16 + group;
#pragma unroll
        for (int ni = 0; ni < 8; ni++) {
            int gn = n_blk + n_w + ni * 8 + tig * 2;
            float2 bbv = *(const float2*)(fcb + gn);
            float2 o0, o1;
            o0.x = acc[mi][ni][0] + bbv.x; o0.y = acc[mi][ni][1] + bbv.y;
            o1.x = acc[mi][ni][2] + bbv.x; o1.y = acc[mi][ni][3] + bbv.y;
            *(float2*)(out + (long)gm0 * V_OUT + gn)       = o0;
            *(float2*)(out + (long)(gm0 + 8) * V_OUT + gn) = o1;
        }
    }
#undef LT_ISSUE
}

// ---------------- launch ----------------
extern "C" void kernel_launch(void* const* d_in, const int* in_sizes, int n_in,
                              void* d_out, int out_size) {
    const int*   src     = (const int*)  d_in[0];
    const int*   trg     = (const int*)  d_in[1];
    const float* enc_emb = (const float*)d_in[2];
    const float* enc_Wih = (const float*)d_in[3];
    const float* enc_Whh = (const float*)d_in[4];
    const float* enc_bih = (const float*)d_in[5];
    const float* enc_bhh = (const float*)d_in[6];
    const float* dec_emb = (const float*)d_in[7];
    const float* dec_Wih = (const float*)d_in[8];
    const float* dec_Whh = (const float*)d_in[9];
    const float* dec_bih = (const float*)d_in[10];
    const float* dec_bhh = (const float*)d_in[11];
    const float* fc_W    = (const float*)d_in[12];
    const float* fc_b    = (const float*)d_in[13];
    float* out = (float*)d_out;

    static bool attr_done = false;
    if (!attr_done) {
        cudaFuncSetAttribute((const void*)gru_rec,
                             cudaFuncAttributeMaxDynamicSharedMemorySize,
                             GR_SMEM_BYTES);
        cudaFuncSetAttribute((const void*)logits_f16,
                             cudaFuncAttributeMaxDynamicSharedMemorySize,
                             LT_SMEM);
        attr_done = true;
    }

    cvt_w<<<V_OUT * H_SZ / (256 * 8), 256>>>(fc_W);
    xg_gemm_all<<<dim3(G_SZ / 64, 80), 256>>>(enc_emb, enc_Wih, enc_bih, src,
                                              dec_emb, dec_Wih, dec_bih, trg);
    gru_rec<<<GR_CTAS, 256, GR_SMEM_BYTES>>>(enc_Whh, enc_bhh, dec_Whh, dec_bhh);
    logits_f16<<<dim3(M_DEC / 128, V_OUT / 128), 128, LT_SMEM>>>(fc_b, out);
}